// round 4
// baseline (speedup 1.0000x reference)
#include <cuda_runtime.h>
#include <math.h>
#include <stdint.h>
#include <stddef.h>

#define BSZ 64
#define CCH 256
#define NPIX 400
#define BN_TOT (BSZ*NPIX)   // 25600

// ---------------- scratch (static device globals; no allocation) ----------------
static __device__ float g_x[(size_t)BN_TOT*256];
static __device__ float g_qg[(size_t)BN_TOT*512];
static __device__ float g_kv[(size_t)BN_TOT*512];
static __device__ float g_attn[(size_t)BN_TOT*256];
static __device__ float g_fused[(size_t)BN_TOT*256];
static __device__ float g_a[(size_t)BN_TOT*256];
static __device__ float g_s[(size_t)BN_TOT*256];
static __device__ float g_y[(size_t)BN_TOT*1024];
static __device__ float g_h[(size_t)BN_TOT*512];
static __device__ float g_f[(size_t)BN_TOT*256];
static __device__ float g_se[BSZ*512];

// ---------------- transpose src (B,C,N) -> x (BN,C) ----------------
__global__ __launch_bounds__(256) void k_transpose(const float* __restrict__ src) {
    __shared__ float sm[32][257];
    int b = blockIdx.y, n0 = blockIdx.x * 32;
    int tid = threadIdx.x;
    for (int j = tid; j < 8192; j += 256) {
        int c = j >> 5, i = j & 31;
        if (n0 + i < NPIX) sm[i][c] = src[(size_t)b*CCH*NPIX + (size_t)c*NPIX + n0 + i];
    }
    __syncthreads();
    for (int j = tid; j < 8192; j += 256) {
        int i = j >> 8, c = j & 255;
        int n = n0 + i;
        if (n < NPIX) g_x[((size_t)(b*NPIX + n))*256 + c] = sm[i][c];
    }
}

// ---------------- tf32 split helpers ----------------
__device__ __forceinline__ unsigned f2tf(float x) {
    unsigned r;
    asm("cvt.rna.tf32.f32 %0, %1;" : "=r"(r) : "f"(x));
    return r;
}

#define MMA_TF32(d, a0,a1,a2,a3, b0,b1) \
    asm volatile("mma.sync.aligned.m16n8k8.row.col.f32.tf32.tf32.f32 " \
        "{%0,%1,%2,%3},{%4,%5,%6,%7},{%8,%9},{%0,%1,%2,%3};" \
        : "+f"(d[0]), "+f"(d[1]), "+f"(d[2]), "+f"(d[3]) \
        : "r"(a0), "r"(a1), "r"(a2), "r"(a3), "r"(b0), "r"(b1))

// ---------------- tensor-core GEMM (3xTF32): C[m][j] = sum_k A[m,k]*W[j,k] + bias[j] ----
// M%128==0, Nc%128==0, K%16==0. Block 128x128, 8 warps of 64x32, k-step 16,
// double-buffered smem with stride-20 padding (conflict-free fragment loads).
#define TSTR 20
__global__ __launch_bounds__(256) void tgemm128(
        const float* __restrict__ A, const float* __restrict__ W,
        const float* __restrict__ bias, float* __restrict__ C,
        int M, int Nc, int K) {
    __shared__ float As[2][128*TSTR];
    __shared__ float Ws[2][128*TSTR];
    const int tid = threadIdx.x;
    const int bm = blockIdx.y * 128, bn = blockIdx.x * 128;
    const int warp = tid >> 5, lane = tid & 31;
    const int wm = (warp & 1) * 64;     // warp M offset within tile
    const int wn = (warp >> 1) * 32;    // warp N offset within tile
    const int gr = lane >> 2, gc = lane & 3;

    // global->smem loader mapping: each thread loads 8 contiguous floats of one row
    const int lr = tid >> 1;            // 0..127
    const int lc = (tid & 1) * 8;       // 0 or 8
    const float* Ap = A + (size_t)(bm + lr)*K + lc;
    const float* Wp = W + (size_t)(bn + lr)*K + lc;

    float acc[4][4][4];
    #pragma unroll
    for (int mt = 0; mt < 4; mt++)
        #pragma unroll
        for (int nt = 0; nt < 4; nt++)
            #pragma unroll
            for (int e = 0; e < 4; e++) acc[mt][nt][e] = 0.f;

    // preload tile 0
    float4 a0v = *(const float4*)(Ap);
    float4 a1v = *(const float4*)(Ap + 4);
    float4 w0v = *(const float4*)(Wp);
    float4 w1v = *(const float4*)(Wp + 4);
    *(float4*)(&As[0][lr*TSTR + lc])     = a0v;
    *(float4*)(&As[0][lr*TSTR + lc + 4]) = a1v;
    *(float4*)(&Ws[0][lr*TSTR + lc])     = w0v;
    *(float4*)(&Ws[0][lr*TSTR + lc + 4]) = w1v;
    __syncthreads();

    int buf = 0;
    for (int k0 = 0; k0 < K; k0 += 16) {
        const bool more = (k0 + 16) < K;
        if (more) {
            a0v = *(const float4*)(Ap + k0 + 16);
            a1v = *(const float4*)(Ap + k0 + 20);
            w0v = *(const float4*)(Wp + k0 + 16);
            w1v = *(const float4*)(Wp + k0 + 20);
        }
        const float* as = As[buf];
        const float* ws = Ws[buf];
        #pragma unroll
        for (int s = 0; s < 16; s += 8) {
            // B fragments for 4 n-tiles (hi/lo split)
            unsigned bh[4][2], bl[4][2];
            #pragma unroll
            for (int nt = 0; nt < 4; nt++) {
                int nrow = wn + nt*8 + gr;
                float b0 = ws[nrow*TSTR + s + gc];
                float b1 = ws[nrow*TSTR + s + gc + 4];
                bh[nt][0] = f2tf(b0); bl[nt][0] = f2tf(b0 - __uint_as_float(bh[nt][0]));
                bh[nt][1] = f2tf(b1); bl[nt][1] = f2tf(b1 - __uint_as_float(bh[nt][1]));
            }
            #pragma unroll
            for (int mt = 0; mt < 4; mt++) {
                int r0 = wm + mt*16 + gr;
                int r1 = r0 + 8;
                float a0 = as[r0*TSTR + s + gc];
                float a1 = as[r1*TSTR + s + gc];
                float a2 = as[r0*TSTR + s + gc + 4];
                float a3 = as[r1*TSTR + s + gc + 4];
                unsigned ah0 = f2tf(a0), ah1 = f2tf(a1), ah2 = f2tf(a2), ah3 = f2tf(a3);
                unsigned al0 = f2tf(a0 - __uint_as_float(ah0));
                unsigned al1 = f2tf(a1 - __uint_as_float(ah1));
                unsigned al2 = f2tf(a2 - __uint_as_float(ah2));
                unsigned al3 = f2tf(a3 - __uint_as_float(ah3));
                #pragma unroll
                for (int nt = 0; nt < 4; nt++) {
                    MMA_TF32(acc[mt][nt], ah0, ah1, ah2, ah3, bh[nt][0], bh[nt][1]);
                    MMA_TF32(acc[mt][nt], al0, al1, al2, al3, bh[nt][0], bh[nt][1]);
                    MMA_TF32(acc[mt][nt], ah0, ah1, ah2, ah3, bl[nt][0], bl[nt][1]);
                }
            }
        }
        if (more) {
            int nb = buf ^ 1;
            *(float4*)(&As[nb][lr*TSTR + lc])     = a0v;
            *(float4*)(&As[nb][lr*TSTR + lc + 4]) = a1v;
            *(float4*)(&Ws[nb][lr*TSTR + lc])     = w0v;
            *(float4*)(&Ws[nb][lr*TSTR + lc + 4]) = w1v;
            __syncthreads();
            buf = nb;
        }
    }

    // epilogue
    #pragma unroll
    for (int nt = 0; nt < 4; nt++) {
        int col = bn + wn + nt*8 + gc*2;
        float b0 = bias ? bias[col]     : 0.f;
        float b1 = bias ? bias[col + 1] : 0.f;
        #pragma unroll
        for (int mt = 0; mt < 4; mt++) {
            int row = bm + wm + mt*16 + gr;
            float2 v0 = make_float2(acc[mt][nt][0] + b0, acc[mt][nt][1] + b1);
            float2 v1 = make_float2(acc[mt][nt][2] + b0, acc[mt][nt][3] + b1);
            *(float2*)(&C[(size_t)row*Nc + col])       = v0;
            *(float2*)(&C[(size_t)(row + 8)*Nc + col]) = v1;
        }
    }
}

// ---------------- linear polarity attention, one block per (b, head) ----------------
// dyn smem: kc[400*64] vv[400*32] kvs[2*64*16] km[64] scl[32] pwl[32] = 40576 floats
#define ATTN_SMEM (40576*4)
__global__ __launch_bounds__(512) void k_attn(const float* __restrict__ pos,
        const float* __restrict__ scale, const float* __restrict__ power) {
    int b = blockIdx.x >> 3, h = blockIdx.x & 7;
    extern __shared__ float sm[];
    float* kc  = sm;             // [n][64]  concat(k_pos, k_neg)
    float* vv  = sm + 25600;     // [n][32]  concat(v1, v2) per head
    float* kvs = sm + 38400;     // [branch][64][16]
    float* km  = sm + 40448;     // [64]
    float* scl = sm + 40512;     // [32]
    float* pwl = sm + 40544;     // [32]
    int tid = threadIdx.x;
    if (tid < 32) {
        scl[tid] = logf(1.f + expf(scale[h*32 + tid]));
        pwl[tid] = 1.f + 4.f / (1.f + expf(-power[h*32 + tid]));
    }
    __syncthreads();

    // Phase A: build kc and v in smem
    for (int i = tid; i < 400*64; i += 512) {
        int n = i >> 6, d = i & 63, dd = d & 31;
        float kraw = (g_kv[((size_t)(b*400 + n))*512 + h*32 + dd] + pos[n*256 + h*32 + dd]) / scl[dd];
        float xv = (d < 32) ? kraw : -kraw;
        kc[i] = (xv > 0.f) ? __powf(fmaxf(xv, 1e-30f), pwl[dd]) : 0.f;
    }
    for (int i = tid; i < 400*32; i += 512) {
        int n = i >> 5, e = i & 31;
        int c = (e < 16) ? (256 + h*16 + e) : (384 + h*16 + (e - 16));
        vv[i] = g_kv[((size_t)(b*400 + n))*512 + c];
    }
    __syncthreads();

    // Phase B: k_mean (threads 0..63)
    if (tid < 64) {
        float s = 0.f;
        for (int n = 0; n < 400; n++) s += kc[n*64 + tid];
        km[tid] = s * (1.f/400.f);
    }
    // Phase C: kv matrices (each thread 4 outputs: fixed d, branch, 4 e's)
    {
        int d = tid & 63, grp = tid >> 6, br = grp >> 2, e0 = (grp & 3) * 4;
        float a0 = 0, a1 = 0, a2 = 0, a3 = 0;
        const float* vb = vv + br*16 + e0;
        #pragma unroll 4
        for (int n = 0; n < 400; n++) {
            float kcv = kc[n*64 + d];
            const float* vp = vb + n*32;
            a0 += kcv * vp[0]; a1 += kcv * vp[1];
            a2 += kcv * vp[2]; a3 += kcv * vp[3];
        }
        const float inv = 1.f/400.f;
        float* o = kvs + br*1024 + d*16 + e0;
        o[0] = a0*inv; o[1] = a1*inv; o[2] = a2*inv; o[3] = a3*inv;
    }
    __syncthreads();

    // Phase D: per-token output
    for (int n = tid; n < 400; n += 512) {
        float os[16], oo[16];
        #pragma unroll
        for (int e = 0; e < 16; e++) { os[e] = 0.f; oo[e] = 0.f; }
        float ss = 0.f, so = 0.f;
        const float* qrow = g_qg + ((size_t)(b*400 + n))*512 + h*32;
        #pragma unroll 2
        for (int dd = 0; dd < 32; dd++) {
            float q = qrow[dd] / scl[dd];
            float p = pwl[dd];
            float qp = (q > 0.f) ? __powf(fmaxf(q, 1e-30f), p) : 0.f;
            float qn = (q < 0.f) ? __powf(fmaxf(-q, 1e-30f), p) : 0.f;
            ss += qp*km[dd] + qn*km[32 + dd];
            so += qn*km[dd] + qp*km[32 + dd];
            const float4* sp  = (const float4*)(kvs + dd*16);
            const float4* sn  = (const float4*)(kvs + (32 + dd)*16);
            const float4* opp = (const float4*)(kvs + 1024 + dd*16);
            const float4* onn = (const float4*)(kvs + 1024 + (32 + dd)*16);
            #pragma unroll
            for (int e4 = 0; e4 < 4; e4++) {
                float4 aa = sp[e4], bb = sn[e4], cc = opp[e4], ee = onn[e4];
                os[e4*4+0] += qp*aa.x + qn*bb.x;
                os[e4*4+1] += qp*aa.y + qn*bb.y;
                os[e4*4+2] += qp*aa.z + qn*bb.z;
                os[e4*4+3] += qp*aa.w + qn*bb.w;
                oo[e4*4+0] += qn*cc.x + qp*ee.x;
                oo[e4*4+1] += qn*cc.y + qp*ee.y;
                oo[e4*4+2] += qn*cc.z + qp*ee.z;
                oo[e4*4+3] += qn*cc.w + qp*ee.w;
            }
        }
        float zs = 1.f/(ss + 1e-6f), zo = 1.f/(so + 1e-6f);
        float* outp = g_attn + ((size_t)(b*400 + n))*256 + h*32;
        #pragma unroll
        for (int e = 0; e < 16; e++) { outp[e] = os[e]*zs; outp[16 + e] = oo[e]*zo; }
    }
}

// ---------------- 5x5 depthwise conv on v (FLAT reshape mapping!) + (attn+vd)*g ----------------
// F = n*256+c  <->  (bh = F/12800, y, x, d) with F = bh*12800 + y*640 + x*32 + d.
#define DWC5_SMEM ((18432 + 800 + 32)*4)
__global__ __launch_bounds__(256) void k_dwc5(const float* __restrict__ w, const float* __restrict__ bias) {
    int b = blockIdx.x >> 3, bh = blockIdx.x & 7;
    extern __shared__ float sm[];
    float* tile = sm;          // [24*24][32]
    float* ws   = sm + 18432;  // [32][25]
    float* wb   = sm + 19232;  // [32]
    int tid = threadIdx.x;
    for (int i = tid; i < 800; i += 256) ws[i] = w[i];
    if (tid < 32) wb[tid] = bias[tid];
    for (int i = tid; i < 576*32; i += 256) {
        int pos = i >> 5, d = i & 31;
        int y = pos / 24 - 2, x = pos % 24 - 2;
        float v = 0.f;
        if (y >= 0 && y < 20 && x >= 0 && x < 20) {
            int F = bh*12800 + y*640 + x*32 + d;
            int n = F >> 8, c = F & 255;
            v = g_kv[((size_t)(b*400 + n))*512 + 256 + c];
        }
        tile[i] = v;
    }
    __syncthreads();
    for (int i = tid; i < 400*32; i += 256) {
        int pos = i >> 5, d = i & 31;
        int y = pos / 20, x = pos % 20;
        float acc = wb[d];
        #pragma unroll
        for (int ky = 0; ky < 5; ky++)
            #pragma unroll
            for (int kx = 0; kx < 5; kx++)
                acc += ws[d*25 + ky*5 + kx] * tile[((y + ky)*24 + (x + kx))*32 + d];
        int F = bh*12800 + y*640 + x*32 + d;
        int n = F >> 8, c = F & 255;
        size_t bn = (size_t)(b*400 + n);
        g_fused[bn*256 + c] = (g_attn[bn*256 + c] + acc) * g_qg[bn*512 + 256 + c];
    }
}

// ---------------- channel LayerNorm 1: s = LN(src + a), output (BN, C) ----------------
__global__ __launch_bounds__(256) void k_ln1(const float* __restrict__ src,
        const float* __restrict__ w, const float* __restrict__ bias) {
    __shared__ float sm[32][257];
    __shared__ float smean[32], srs[32];
    int b = blockIdx.y, n0 = blockIdx.x * 32;
    int tid = threadIdx.x;
    for (int j = tid; j < 8192; j += 256) {
        int c = j >> 5, i = j & 31;
        if (n0 + i < 400) sm[i][c] = src[(size_t)b*102400 + c*400 + n0 + i];
    }
    __syncthreads();
    for (int j = tid; j < 8192; j += 256) {
        int i = j >> 8, c = j & 255;
        if (n0 + i < 400) sm[i][c] += g_a[((size_t)(b*400 + n0 + i))*256 + c];
    }
    __syncthreads();
    int warp = tid >> 5, lane = tid & 31;
    for (int i = warp; i < 32; i += 8) {
        if (n0 + i < 400) {
            float s1 = 0.f, s2 = 0.f;
            #pragma unroll
            for (int t = 0; t < 8; t++) { float v = sm[i][lane + t*32]; s1 += v; s2 += v*v; }
            #pragma unroll
            for (int off = 16; off > 0; off >>= 1) {
                s1 += __shfl_xor_sync(0xffffffffu, s1, off);
                s2 += __shfl_xor_sync(0xffffffffu, s2, off);
            }
            if (lane == 0) {
                float mu = s1 * (1.f/256.f);
                float var = s2 * (1.f/256.f) - mu*mu;
                smean[i] = mu; srs[i] = rsqrtf(var + 1e-6f);
            }
        }
    }
    __syncthreads();
    for (int j = tid; j < 8192; j += 256) {
        int i = j >> 8, c = j & 255;
        int n = n0 + i;
        if (n < 400)
            g_s[((size_t)(b*400 + n))*256 + c] = w[c]*(sm[i][c] - smean[i])*srs[i] + bias[c];
    }
}

// ---------------- SE gate (merged): mean over src spatial, then sigmoid(se_w . mean) ----------------
__global__ __launch_bounds__(512) void k_se(const float* __restrict__ src,
        const float* __restrict__ sew) {
    __shared__ float m[256];
    int b = blockIdx.x, tid = threadIdx.x;
    int warp = tid >> 5, lane = tid & 31;
    for (int c = warp; c < 256; c += 16) {
        float s = 0.f;
        for (int n = lane; n < 400; n += 32) s += src[(size_t)b*102400 + c*400 + n];
        #pragma unroll
        for (int off = 16; off > 0; off >>= 1) s += __shfl_xor_sync(0xffffffffu, s, off);
        if (lane == 0) m[c] = s * (1.f/400.f);
    }
    __syncthreads();
    float s = 0.f;
    const float* wr = sew + (size_t)tid*256;
    #pragma unroll 4
    for (int c = 0; c < 256; c++) s += wr[c]*m[c];
    g_se[b*512 + tid] = 1.f/(1.f + expf(-s));
}

// ---------------- 3x3 depthwise + exact GELU gate + SE ----------------
#define DW3_SMEM ((15488*2 + 288*2)*4)
__global__ __launch_bounds__(256) void k_dw3(const float* __restrict__ w) {
    int b = blockIdx.y, jt = blockIdx.x;  // jt in [0,16): tile of 32 channels
    extern __shared__ float sm[];
    float* t1 = sm;                 // [22*22][32] x1 half
    float* t2 = sm + 15488;         // [22*22][32] x2 half
    float* w1 = sm + 30976;         // [32][9]
    float* w2 = sm + 31264;         // [32][9]
    int tid = threadIdx.x;
    for (int i = tid; i < 288; i += 256) {
        int jj = i / 9, t = i % 9;
        w1[i] = w[(jt*32 + jj)*9 + t];
        w2[i] = w[(512 + jt*32 + jj)*9 + t];
    }
    for (int i = tid; i < 484*32; i += 256) {
        int pos = i >> 5, jj = i & 31;
        int y = pos / 22 - 1, x = pos % 22 - 1;
        float v1 = 0.f, v2 = 0.f;
        if (y >= 0 && y < 20 && x >= 0 && x < 20) {
            size_t base = ((size_t)(b*400 + y*20 + x))*1024 + jt*32 + jj;
            v1 = g_y[base]; v2 = g_y[base + 512];
        }
        t1[i] = v1; t2[i] = v2;
    }
    __syncthreads();
    for (int i = tid; i < 400*32; i += 256) {
        int pos = i >> 5, jj = i & 31;
        int y = pos / 20, x = pos % 20;
        float d1 = 0.f, d2 = 0.f;
        #pragma unroll
        for (int ky = 0; ky < 3; ky++)
            #pragma unroll
            for (int kx = 0; kx < 3; kx++) {
                int tp = ((y + ky)*22 + (x + kx))*32 + jj;
                d1 += w1[jj*9 + ky*3 + kx] * t1[tp];
                d2 += w2[jj*9 + ky*3 + kx] * t2[tp];
            }
        float ge = 0.5f * d1 * (1.f + erff(d1 * 0.70710678118654752f));
        g_h[((size_t)(b*400 + pos))*512 + jt*32 + jj] = ge * d2 * g_se[b*512 + jt*32 + jj];
    }
}

// ---------------- LN2: out = LN(s + f), output NCHW (B,C,N) ----------------
__global__ __launch_bounds__(256) void k_ln2(float* __restrict__ out,
        const float* __restrict__ w, const float* __restrict__ bias) {
    __shared__ float sm[32][257];
    __shared__ float smean[32], srs[32];
    int b = blockIdx.y, n0 = blockIdx.x * 32;
    int tid = threadIdx.x;
    for (int j = tid; j < 8192; j += 256) {
        int i = j >> 8, c = j & 255;
        int n = n0 + i;
        if (n < 400) {
            size_t bn = (size_t)(b*400 + n);
            sm[i][c] = g_s[bn*256 + c] + g_f[bn*256 + c];
        }
    }
    __syncthreads();
    int warp = tid >> 5, lane = tid & 31;
    for (int i = warp; i < 32; i += 8) {
        if (n0 + i < 400) {
            float s1 = 0.f, s2 = 0.f;
            #pragma unroll
            for (int t = 0; t < 8; t++) { float v = sm[i][lane + t*32]; s1 += v; s2 += v*v; }
            #pragma unroll
            for (int off = 16; off > 0; off >>= 1) {
                s1 += __shfl_xor_sync(0xffffffffu, s1, off);
                s2 += __shfl_xor_sync(0xffffffffu, s2, off);
            }
            if (lane == 0) {
                float mu = s1 * (1.f/256.f);
                float var = s2 * (1.f/256.f) - mu*mu;
                smean[i] = mu; srs[i] = rsqrtf(var + 1e-6f);
            }
        }
    }
    __syncthreads();
    for (int j = tid; j < 8192; j += 256) {
        int c = j >> 5, i = j & 31;
        int n = n0 + i;
        if (n < 400)
            out[(size_t)b*102400 + c*400 + n] = w[c]*(sm[i][c] - smean[i])*srs[i] + bias[c];
    }
}

// ---------------- host launch ----------------
extern "C" void kernel_launch(void* const* d_in, const int* in_sizes, int n_in,
                              void* d_out, int out_size) {
    const float* src    = (const float*)d_in[0];
    const float* qg_w   = (const float*)d_in[1];
    const float* qg_b   = (const float*)d_in[2];
    const float* kv_w   = (const float*)d_in[3];
    const float* kv_b   = (const float*)d_in[4];
    const float* proj_w = (const float*)d_in[5];
    const float* proj_b = (const float*)d_in[6];
    const float* dwc_w  = (const float*)d_in[7];
    const float* dwc_b  = (const float*)d_in[8];
    const float* power  = (const float*)d_in[9];
    const float* scale  = (const float*)d_in[10];
    const float* pos    = (const float*)d_in[11];
    const float* pin_w  = (const float*)d_in[12];
    const float* dw_w   = (const float*)d_in[13];
    const float* se_w   = (const float*)d_in[14];
    const float* pout_w = (const float*)d_in[15];
    const float* ln1_w  = (const float*)d_in[16];
    const float* ln1_b  = (const float*)d_in[17];
    const float* ln2_w  = (const float*)d_in[18];
    const float* ln2_b  = (const float*)d_in[19];
    float* out = (float*)d_out;

    float *px, *pqg, *pkv, *pfused, *pa, *ps, *py, *ph, *pf;
    cudaGetSymbolAddress((void**)&px, g_x);
    cudaGetSymbolAddress((void**)&pqg, g_qg);
    cudaGetSymbolAddress((void**)&pkv, g_kv);
    cudaGetSymbolAddress((void**)&pfused, g_fused);
    cudaGetSymbolAddress((void**)&pa, g_a);
    cudaGetSymbolAddress((void**)&ps, g_s);
    cudaGetSymbolAddress((void**)&py, g_y);
    cudaGetSymbolAddress((void**)&ph, g_h);
    cudaGetSymbolAddress((void**)&pf, g_f);

    cudaFuncSetAttribute(k_attn, cudaFuncAttributeMaxDynamicSharedMemorySize, ATTN_SMEM);
    cudaFuncSetAttribute(k_dwc5, cudaFuncAttributeMaxDynamicSharedMemorySize, DWC5_SMEM);
    cudaFuncSetAttribute(k_dw3,  cudaFuncAttributeMaxDynamicSharedMemorySize, DW3_SMEM);

    k_transpose<<<dim3(13, 64), 256>>>(src);

    tgemm128<<<dim3(4, 200), 256>>>(px, qg_w, qg_b, pqg, BN_TOT, 512, 256);
    tgemm128<<<dim3(4, 200), 256>>>(px, kv_w, kv_b, pkv, BN_TOT, 512, 256);

    k_attn<<<512, 512, ATTN_SMEM>>>(pos, scale, power);
    k_dwc5<<<512, 256, DWC5_SMEM>>>(dwc_w, dwc_b);

    tgemm128<<<dim3(2, 200), 256>>>(pfused, proj_w, proj_b, pa, BN_TOT, 256, 256);
    k_ln1<<<dim3(13, 64), 256>>>(src, ln1_w, ln1_b);

    k_se<<<64, 512>>>(src, se_w);

    tgemm128<<<dim3(8, 200), 256>>>(ps, pin_w, nullptr, py, BN_TOT, 1024, 256);
    k_dw3<<<dim3(16, 64), 256, DW3_SMEM>>>(dw_w);
    tgemm128<<<dim3(2, 200), 256>>>(ph, pout_w, nullptr, pf, BN_TOT, 256, 512);

    k_ln2<<<dim3(13, 64), 256>>>(out, ln2_w, ln2_b);
}

// round 8
// speedup vs baseline: 1.3266x; 1.3266x over previous
#include <cuda_runtime.h>
#include <math.h>
#include <stdint.h>
#include <stddef.h>

#define BSZ 64
#define CCH 256
#define NPIX 400
#define BN_TOT (BSZ*NPIX)   // 25600

// ---------------- scratch (static device globals; no allocation) ----------------
static __device__ float g_x[(size_t)BN_TOT*256];
static __device__ float g_qg[(size_t)BN_TOT*512];
static __device__ float g_kv[(size_t)BN_TOT*512];
static __device__ float g_attn[(size_t)BN_TOT*256];
static __device__ float g_fused[(size_t)BN_TOT*256];
static __device__ float g_a[(size_t)BN_TOT*256];
static __device__ float g_s[(size_t)BN_TOT*256];
static __device__ float g_y[(size_t)BN_TOT*1024];
static __device__ float g_h[(size_t)BN_TOT*512];
static __device__ float g_f[(size_t)BN_TOT*256];
static __device__ float g_se[BSZ*512];

// ---------------- transpose src (B,C,N) -> x (BN,C) ----------------
__global__ __launch_bounds__(256) void k_transpose(const float* __restrict__ src) {
    __shared__ float sm[32][257];
    int b = blockIdx.y, n0 = blockIdx.x * 32;
    int tid = threadIdx.x;
    for (int j = tid; j < 8192; j += 256) {
        int c = j >> 5, i = j & 31;
        if (n0 + i < NPIX) sm[i][c] = src[(size_t)b*CCH*NPIX + (size_t)c*NPIX + n0 + i];
    }
    __syncthreads();
    for (int j = tid; j < 8192; j += 256) {
        int i = j >> 8, c = j & 255;
        int n = n0 + i;
        if (n < NPIX) g_x[((size_t)(b*NPIX + n))*256 + c] = sm[i][c];
    }
}

// ---------------- tf32 helpers ----------------
__device__ __forceinline__ unsigned f2tf(float x) {
    unsigned r;
    asm("cvt.rna.tf32.f32 %0, %1;" : "=r"(r) : "f"(x));
    return r;
}

#define MMA_TF32(d, a0,a1,a2,a3, b0,b1) \
    asm volatile("mma.sync.aligned.m16n8k8.row.col.f32.tf32.tf32.f32 " \
        "{%0,%1,%2,%3},{%4,%5,%6,%7},{%8,%9},{%0,%1,%2,%3};" \
        : "+f"(d[0]), "+f"(d[1]), "+f"(d[2]), "+f"(d[3]) \
        : "r"(a0), "r"(a1), "r"(a2), "r"(a3), "r"(b0), "r"(b1))

// ---------------- tensor-core GEMM: C[m][j] = sum_k A[m,k]*W[j,k] + bias[j] ----------
// SPLIT=3: Markidis 3-term tf32 split (rel err ~1e-7). SPLIT=1: plain tf32 (~1e-4).
// M%128==0, K%16==0, grid.x covers the desired column range; Nc is ONLY the C
// row stride, so offset W/bias/C pointers select a column sub-range.
// Block 128x128, 8 warps of 64x32, k-step 16, double-buffered smem,
// stride-20 padding (conflict-free fragment loads).
#define TSTR 20
template<int SPLIT>
__global__ __launch_bounds__(256) void tgemm128(
        const float* __restrict__ A, const float* __restrict__ W,
        const float* __restrict__ bias, float* __restrict__ C,
        int M, int Nc, int K) {
    __shared__ float As[2][128*TSTR];
    __shared__ float Ws[2][128*TSTR];
    const int tid = threadIdx.x;
    const int bm = blockIdx.y * 128, bn = blockIdx.x * 128;
    const int warp = tid >> 5, lane = tid & 31;
    const int wm = (warp & 1) * 64;     // warp M offset within tile
    const int wn = (warp >> 1) * 32;    // warp N offset within tile
    const int gr = lane >> 2, gc = lane & 3;

    const int lr = tid >> 1;            // 0..127
    const int lc = (tid & 1) * 8;       // 0 or 8
    const float* Ap = A + (size_t)(bm + lr)*K + lc;
    const float* Wp = W + (size_t)(bn + lr)*K + lc;

    float acc[4][4][4];
    #pragma unroll
    for (int mt = 0; mt < 4; mt++)
        #pragma unroll
        for (int nt = 0; nt < 4; nt++)
            #pragma unroll
            for (int e = 0; e < 4; e++) acc[mt][nt][e] = 0.f;

    // preload tile 0
    float4 a0v = *(const float4*)(Ap);
    float4 a1v = *(const float4*)(Ap + 4);
    float4 w0v = *(const float4*)(Wp);
    float4 w1v = *(const float4*)(Wp + 4);
    *(float4*)(&As[0][lr*TSTR + lc])     = a0v;
    *(float4*)(&As[0][lr*TSTR + lc + 4]) = a1v;
    *(float4*)(&Ws[0][lr*TSTR + lc])     = w0v;
    *(float4*)(&Ws[0][lr*TSTR + lc + 4]) = w1v;
    __syncthreads();

    int buf = 0;
    for (int k0 = 0; k0 < K; k0 += 16) {
        const bool more = (k0 + 16) < K;
        if (more) {
            a0v = *(const float4*)(Ap + k0 + 16);
            a1v = *(const float4*)(Ap + k0 + 20);
            w0v = *(const float4*)(Wp + k0 + 16);
            w1v = *(const float4*)(Wp + k0 + 20);
        }
        const float* as = As[buf];
        const float* ws = Ws[buf];
        #pragma unroll
        for (int s = 0; s < 16; s += 8) {
            unsigned bh[4][2], bl[4][2];
            #pragma unroll
            for (int nt = 0; nt < 4; nt++) {
                int nrow = wn + nt*8 + gr;
                float b0 = ws[nrow*TSTR + s + gc];
                float b1 = ws[nrow*TSTR + s + gc + 4];
                bh[nt][0] = f2tf(b0);
                bh[nt][1] = f2tf(b1);
                if (SPLIT == 3) {
                    bl[nt][0] = f2tf(b0 - __uint_as_float(bh[nt][0]));
                    bl[nt][1] = f2tf(b1 - __uint_as_float(bh[nt][1]));
                }
            }
            #pragma unroll
            for (int mt = 0; mt < 4; mt++) {
                int r0 = wm + mt*16 + gr;
                int r1 = r0 + 8;
                float a0 = as[r0*TSTR + s + gc];
                float a1 = as[r1*TSTR + s + gc];
                float a2 = as[r0*TSTR + s + gc + 4];
                float a3 = as[r1*TSTR + s + gc + 4];
                unsigned ah0 = f2tf(a0), ah1 = f2tf(a1), ah2 = f2tf(a2), ah3 = f2tf(a3);
                unsigned al0 = 0, al1 = 0, al2 = 0, al3 = 0;
                if (SPLIT == 3) {
                    al0 = f2tf(a0 - __uint_as_float(ah0));
                    al1 = f2tf(a1 - __uint_as_float(ah1));
                    al2 = f2tf(a2 - __uint_as_float(ah2));
                    al3 = f2tf(a3 - __uint_as_float(ah3));
                }
                #pragma unroll
                for (int nt = 0; nt < 4; nt++) {
                    MMA_TF32(acc[mt][nt], ah0, ah1, ah2, ah3, bh[nt][0], bh[nt][1]);
                    if (SPLIT == 3) {
                        MMA_TF32(acc[mt][nt], al0, al1, al2, al3, bh[nt][0], bh[nt][1]);
                        MMA_TF32(acc[mt][nt], ah0, ah1, ah2, ah3, bl[nt][0], bl[nt][1]);
                    }
                }
            }
        }
        if (more) {
            int nb = buf ^ 1;
            *(float4*)(&As[nb][lr*TSTR + lc])     = a0v;
            *(float4*)(&As[nb][lr*TSTR + lc + 4]) = a1v;
            *(float4*)(&Ws[nb][lr*TSTR + lc])     = w0v;
            *(float4*)(&Ws[nb][lr*TSTR + lc + 4]) = w1v;
            __syncthreads();
            buf = nb;
        }
    }

    #pragma unroll
    for (int nt = 0; nt < 4; nt++) {
        int col = bn + wn + nt*8 + gc*2;
        float b0 = bias ? bias[col]     : 0.f;
        float b1 = bias ? bias[col + 1] : 0.f;
        #pragma unroll
        for (int mt = 0; mt < 4; mt++) {
            int row = bm + wm + mt*16 + gr;
            float2 v0 = make_float2(acc[mt][nt][0] + b0, acc[mt][nt][1] + b1);
            float2 v1 = make_float2(acc[mt][nt][2] + b0, acc[mt][nt][3] + b1);
            *(float2*)(&C[(size_t)row*Nc + col])       = v0;
            *(float2*)(&C[(size_t)(row + 8)*Nc + col]) = v1;
        }
    }
}

// ---------------- linear polarity attention, one block per (b, head) ----------------
// Polarity trick: for any x exactly one of relu(x)^p, relu(-x)^p is nonzero.
// Store a SIGNED magnitude ks = copysign(|k|^p, k); k_pos=max(ks,0), k_neg=max(-ks,0).
// Halves MUFU work AND halves smem (111KB -> 2 CTAs/SM, occupancy 2x).
// dyn smem: ks[400*32] vv[400*32] kvs[2*64*16] km[64] scl[32] pwl[32] = 27776 floats
#define ATTN_SMEM (27776*4)
__global__ __launch_bounds__(512,2) void k_attn(const float* __restrict__ pos,
        const float* __restrict__ scale, const float* __restrict__ power) {
    int b = blockIdx.x >> 3, h = blockIdx.x & 7;
    extern __shared__ float sm[];
    float* ks  = sm;             // [n][32]  signed |k|^p
    float* vv  = sm + 12800;     // [n][32]  concat(v1, v2) per head
    float* kvs = sm + 25600;     // [branch][64][16]
    float* km  = sm + 27648;     // [64]
    float* scl = sm + 27712;     // [32]
    float* pwl = sm + 27744;     // [32]
    int tid = threadIdx.x;
    if (tid < 32) {
        scl[tid] = logf(1.f + expf(scale[h*32 + tid]));
        pwl[tid] = 1.f + 4.f / (1.f + expf(-power[h*32 + tid]));
    }
    __syncthreads();

    // Phase A: signed magnitudes (one powf per (n,dd))
    for (int i = tid; i < 400*32; i += 512) {
        int n = i >> 5, dd = i & 31;
        float kraw = (g_kv[((size_t)(b*400 + n))*512 + h*32 + dd] + pos[n*256 + h*32 + dd]) / scl[dd];
        float av = fabsf(kraw);
        float pw = (av > 0.f) ? __powf(fmaxf(av, 1e-30f), pwl[dd]) : 0.f;
        ks[i] = (kraw > 0.f) ? pw : ((kraw < 0.f) ? -pw : 0.f);
    }
    for (int i = tid; i < 400*32; i += 512) {
        int n = i >> 5, e = i & 31;
        int c = (e < 16) ? (256 + h*16 + e) : (384 + h*16 + (e - 16));
        vv[i] = g_kv[((size_t)(b*400 + n))*512 + c];
    }
    __syncthreads();

    // Phase B: k_mean (threads 0..63); d<32 -> k_pos row, d>=32 -> k_neg row
    if (tid < 64) {
        int dd = tid & 31; bool pos_row = tid < 32;
        float s = 0.f;
        for (int n = 0; n < 400; n++) {
            float v = ks[n*32 + dd];
            s += pos_row ? fmaxf(v, 0.f) : fmaxf(-v, 0.f);
        }
        km[tid] = s * (1.f/400.f);
    }
    // Phase C: kv matrices (each thread 4 outputs: fixed d, branch, 4 e's)
    {
        int d = tid & 63, grp = tid >> 6, br = grp >> 2, e0 = (grp & 3) * 4;
        int dd = d & 31; bool pos_row = d < 32;
        float a0 = 0, a1 = 0, a2 = 0, a3 = 0;
        const float* vb = vv + br*16 + e0;
        #pragma unroll 4
        for (int n = 0; n < 400; n++) {
            float v = ks[n*32 + dd];
            float kcv = pos_row ? fmaxf(v, 0.f) : fmaxf(-v, 0.f);
            const float* vp = vb + n*32;
            a0 += kcv * vp[0]; a1 += kcv * vp[1];
            a2 += kcv * vp[2]; a3 += kcv * vp[3];
        }
        const float inv = 1.f/400.f;
        float* o = kvs + br*1024 + d*16 + e0;
        o[0] = a0*inv; o[1] = a1*inv; o[2] = a2*inv; o[3] = a3*inv;
    }
    __syncthreads();

    // Phase D: per-token output (one powf per dd; operand selected by sign)
    for (int n = tid; n < 400; n += 512) {
        float os[16], oo[16];
        #pragma unroll
        for (int e = 0; e < 16; e++) { os[e] = 0.f; oo[e] = 0.f; }
        float ss = 0.f, so = 0.f;
        const float* qrow = g_qg + ((size_t)(b*400 + n))*512 + h*32;
        #pragma unroll 2
        for (int dd = 0; dd < 32; dd++) {
            float q = qrow[dd] / scl[dd];
            float aq = fabsf(q);
            float pw = (aq > 0.f) ? __powf(fmaxf(aq, 1e-30f), pwl[dd]) : 0.f;
            bool posq = (q > 0.f);
            // nonzero q-power row: dd if posq else 32+dd; opp branch mirrors.
            ss += pw * (posq ? km[dd] : km[32 + dd]);
            so += pw * (posq ? km[32 + dd] : km[dd]);
            const float4* sp = (const float4*)(kvs + (posq ? dd : 32 + dd)*16);
            const float4* op = (const float4*)(kvs + 1024 + (posq ? 32 + dd : dd)*16);
            #pragma unroll
            for (int e4 = 0; e4 < 4; e4++) {
                float4 aa = sp[e4], cc = op[e4];
                os[e4*4+0] += pw*aa.x; os[e4*4+1] += pw*aa.y;
                os[e4*4+2] += pw*aa.z; os[e4*4+3] += pw*aa.w;
                oo[e4*4+0] += pw*cc.x; oo[e4*4+1] += pw*cc.y;
                oo[e4*4+2] += pw*cc.z; oo[e4*4+3] += pw*cc.w;
            }
        }
        float zs = 1.f/(ss + 1e-6f), zo = 1.f/(so + 1e-6f);
        float* outp = g_attn + ((size_t)(b*400 + n))*256 + h*32;
        #pragma unroll
        for (int e = 0; e < 16; e++) { outp[e] = os[e]*zs; outp[16 + e] = oo[e]*zo; }
    }
}

// ---------------- 5x5 depthwise conv on v (FLAT reshape mapping!) + (attn+vd)*g ----------------
// F = n*256+c  <->  (bh = F/12800, y, x, d) with F = bh*12800 + y*640 + x*32 + d.
#define DWC5_SMEM ((18432 + 800 + 32)*4)
__global__ __launch_bounds__(256) void k_dwc5(const float* __restrict__ w, const float* __restrict__ bias) {
    int b = blockIdx.x >> 3, bh = blockIdx.x & 7;
    extern __shared__ float sm[];
    float* tile = sm;          // [24*24][32]
    float* ws   = sm + 18432;  // [32][25]
    float* wb   = sm + 19232;  // [32]
    int tid = threadIdx.x;
    for (int i = tid; i < 800; i += 256) ws[i] = w[i];
    if (tid < 32) wb[tid] = bias[tid];
    for (int i = tid; i < 576*32; i += 256) {
        int pos = i >> 5, d = i & 31;
        int y = pos / 24 - 2, x = pos % 24 - 2;
        float v = 0.f;
        if (y >= 0 && y < 20 && x >= 0 && x < 20) {
            int F = bh*12800 + y*640 + x*32 + d;
            int n = F >> 8, c = F & 255;
            v = g_kv[((size_t)(b*400 + n))*512 + 256 + c];
        }
        tile[i] = v;
    }
    __syncthreads();
    for (int i = tid; i < 400*32; i += 256) {
        int pos = i >> 5, d = i & 31;
        int y = pos / 20, x = pos % 20;
        float acc = wb[d];
        #pragma unroll
        for (int ky = 0; ky < 5; ky++)
            #pragma unroll
            for (int kx = 0; kx < 5; kx++)
                acc += ws[d*25 + ky*5 + kx] * tile[((y + ky)*24 + (x + kx))*32 + d];
        int F = bh*12800 + y*640 + x*32 + d;
        int n = F >> 8, c = F & 255;
        size_t bn = (size_t)(b*400 + n);
        g_fused[bn*256 + c] = (g_attn[bn*256 + c] + acc) * g_qg[bn*512 + 256 + c];
    }
}

// ---------------- channel LayerNorm 1: s = LN(src + a), output (BN, C) ----------------
__global__ __launch_bounds__(256) void k_ln1(const float* __restrict__ src,
        const float* __restrict__ w, const float* __restrict__ bias) {
    __shared__ float sm[32][257];
    __shared__ float smean[32], srs[32];
    int b = blockIdx.y, n0 = blockIdx.x * 32;
    int tid = threadIdx.x;
    for (int j = tid; j < 8192; j += 256) {
        int c = j >> 5, i = j & 31;
        if (n0 + i < 400) sm[i][c] = src[(size_t)b*102400 + c*400 + n0 + i];
    }
    __syncthreads();
    for (int j = tid; j < 8192; j += 256) {
        int i = j >> 8, c = j & 255;
        if (n0 + i < 400) sm[i][c] += g_a[((size_t)(b*400 + n0 + i))*256 + c];
    }
    __syncthreads();
    int warp = tid >> 5, lane = tid & 31;
    for (int i = warp; i < 32; i += 8) {
        if (n0 + i < 400) {
            float s1 = 0.f, s2 = 0.f;
            #pragma unroll
            for (int t = 0; t < 8; t++) { float v = sm[i][lane + t*32]; s1 += v; s2 += v*v; }
            #pragma unroll
            for (int off = 16; off > 0; off >>= 1) {
                s1 += __shfl_xor_sync(0xffffffffu, s1, off);
                s2 += __shfl_xor_sync(0xffffffffu, s2, off);
            }
            if (lane == 0) {
                float mu = s1 * (1.f/256.f);
                float var = s2 * (1.f/256.f) - mu*mu;
                smean[i] = mu; srs[i] = rsqrtf(var + 1e-6f);
            }
        }
    }
    __syncthreads();
    for (int j = tid; j < 8192; j += 256) {
        int i = j >> 8, c = j & 255;
        int n = n0 + i;
        if (n < 400)
            g_s[((size_t)(b*400 + n))*256 + c] = w[c]*(sm[i][c] - smean[i])*srs[i] + bias[c];
    }
}

// ---------------- SE gate (merged): mean over src spatial, then sigmoid(se_w . mean) ----------------
__global__ __launch_bounds__(512) void k_se(const float* __restrict__ src,
        const float* __restrict__ sew) {
    __shared__ float m[256];
    int b = blockIdx.x, tid = threadIdx.x;
    int warp = tid >> 5, lane = tid & 31;
    for (int c = warp; c < 256; c += 16) {
        float s = 0.f;
        for (int n = lane; n < 400; n += 32) s += src[(size_t)b*102400 + c*400 + n];
        #pragma unroll
        for (int off = 16; off > 0; off >>= 1) s += __shfl_xor_sync(0xffffffffu, s, off);
        if (lane == 0) m[c] = s * (1.f/400.f);
    }
    __syncthreads();
    float s = 0.f;
    const float* wr = sew + (size_t)tid*256;
    #pragma unroll 4
    for (int c = 0; c < 256; c++) s += wr[c]*m[c];
    g_se[b*512 + tid] = 1.f/(1.f + expf(-s));
}

// ---------------- 3x3 depthwise + exact GELU gate + SE ----------------
#define DW3_SMEM ((15488*2 + 288*2)*4)
__global__ __launch_bounds__(256) void k_dw3(const float* __restrict__ w) {
    int b = blockIdx.y, jt = blockIdx.x;  // jt in [0,16): tile of 32 channels
    extern __shared__ float sm[];
    float* t1 = sm;                 // [22*22][32] x1 half
    float* t2 = sm + 15488;         // [22*22][32] x2 half
    float* w1 = sm + 30976;         // [32][9]
    float* w2 = sm + 31264;         // [32][9]
    int tid = threadIdx.x;
    for (int i = tid; i < 288; i += 256) {
        int jj = i / 9, t = i % 9;
        w1[i] = w[(jt*32 + jj)*9 + t];
        w2[i] = w[(512 + jt*32 + jj)*9 + t];
    }
    for (int i = tid; i < 484*32; i += 256) {
        int pos = i >> 5, jj = i & 31;
        int y = pos / 22 - 1, x = pos % 22 - 1;
        float v1 = 0.f, v2 = 0.f;
        if (y >= 0 && y < 20 && x >= 0 && x < 20) {
            size_t base = ((size_t)(b*400 + y*20 + x))*1024 + jt*32 + jj;
            v1 = g_y[base]; v2 = g_y[base + 512];
        }
        t1[i] = v1; t2[i] = v2;
    }
    __syncthreads();
    for (int i = tid; i < 400*32; i += 256) {
        int pos = i >> 5, jj = i & 31;
        int y = pos / 20, x = pos % 20;
        float d1 = 0.f, d2 = 0.f;
        #pragma unroll
        for (int ky = 0; ky < 3; ky++)
            #pragma unroll
            for (int kx = 0; kx < 3; kx++) {
                int tp = ((y + ky)*22 + (x + kx))*32 + jj;
                d1 += w1[jj*9 + ky*3 + kx] * t1[tp];
                d2 += w2[jj*9 + ky*3 + kx] * t2[tp];
            }
        float ge = 0.5f * d1 * (1.f + erff(d1 * 0.70710678118654752f));
        g_h[((size_t)(b*400 + pos))*512 + jt*32 + jj] = ge * d2 * g_se[b*512 + jt*32 + jj];
    }
}

// ---------------- LN2: out = LN(s + f), output NCHW (B,C,N) ----------------
__global__ __launch_bounds__(256) void k_ln2(float* __restrict__ out,
        const float* __restrict__ w, const float* __restrict__ bias) {
    __shared__ float sm[32][257];
    __shared__ float smean[32], srs[32];
    int b = blockIdx.y, n0 = blockIdx.x * 32;
    int tid = threadIdx.x;
    for (int j = tid; j < 8192; j += 256) {
        int i = j >> 8, c = j & 255;
        int n = n0 + i;
        if (n < 400) {
            size_t bn = (size_t)(b*400 + n);
            sm[i][c] = g_s[bn*256 + c] + g_f[bn*256 + c];
        }
    }
    __syncthreads();
    int warp = tid >> 5, lane = tid & 31;
    for (int i = warp; i < 32; i += 8) {
        if (n0 + i < 400) {
            float s1 = 0.f, s2 = 0.f;
            #pragma unroll
            for (int t = 0; t < 8; t++) { float v = sm[i][lane + t*32]; s1 += v; s2 += v*v; }
            #pragma unroll
            for (int off = 16; off > 0; off >>= 1) {
                s1 += __shfl_xor_sync(0xffffffffu, s1, off);
                s2 += __shfl_xor_sync(0xffffffffu, s2, off);
            }
            if (lane == 0) {
                float mu = s1 * (1.f/256.f);
                float var = s2 * (1.f/256.f) - mu*mu;
                smean[i] = mu; srs[i] = rsqrtf(var + 1e-6f);
            }
        }
    }
    __syncthreads();
    for (int j = tid; j < 8192; j += 256) {
        int c = j >> 5, i = j & 31;
        int n = n0 + i;
        if (n < 400)
            out[(size_t)b*102400 + c*400 + n] = w[c]*(sm[i][c] - smean[i])*srs[i] + bias[c];
    }
}

// ---------------- host launch ----------------
extern "C" void kernel_launch(void* const* d_in, const int* in_sizes, int n_in,
                              void* d_out, int out_size) {
    const float* src    = (const float*)d_in[0];
    const float* qg_w   = (const float*)d_in[1];
    const float* qg_b   = (const float*)d_in[2];
    const float* kv_w   = (const float*)d_in[3];
    const float* kv_b   = (const float*)d_in[4];
    const float* proj_w = (const float*)d_in[5];
    const float* proj_b = (const float*)d_in[6];
    const float* dwc_w  = (const float*)d_in[7];
    const float* dwc_b  = (const float*)d_in[8];
    const float* power  = (const float*)d_in[9];
    const float* scale  = (const float*)d_in[10];
    const float* pos    = (const float*)d_in[11];
    const float* pin_w  = (const float*)d_in[12];
    const float* dw_w   = (const float*)d_in[13];
    const float* se_w   = (const float*)d_in[14];
    const float* pout_w = (const float*)d_in[15];
    const float* ln1_w  = (const float*)d_in[16];
    const float* ln1_b  = (const float*)d_in[17];
    const float* ln2_w  = (const float*)d_in[18];
    const float* ln2_b  = (const float*)d_in[19];
    float* out = (float*)d_out;

    float *px, *pqg, *pkv, *pfused, *pa, *ps, *py, *ph, *pf;
    cudaGetSymbolAddress((void**)&px, g_x);
    cudaGetSymbolAddress((void**)&pqg, g_qg);
    cudaGetSymbolAddress((void**)&pkv, g_kv);
    cudaGetSymbolAddress((void**)&pfused, g_fused);
    cudaGetSymbolAddress((void**)&pa, g_a);
    cudaGetSymbolAddress((void**)&ps, g_s);
    cudaGetSymbolAddress((void**)&py, g_y);
    cudaGetSymbolAddress((void**)&ph, g_h);
    cudaGetSymbolAddress((void**)&pf, g_f);

    cudaFuncSetAttribute(k_attn, cudaFuncAttributeMaxDynamicSharedMemorySize, ATTN_SMEM);
    cudaFuncSetAttribute(k_dwc5, cudaFuncAttributeMaxDynamicSharedMemorySize, DWC5_SMEM);
    cudaFuncSetAttribute(k_dw3,  cudaFuncAttributeMaxDynamicSharedMemorySize, DW3_SMEM);

    k_transpose<<<dim3(13, 64), 256>>>(src);

    // q half (cols 0-255) feeds ^p -> split-3; g half (cols 256-511) is a
    // linear gate -> split-1. Same for k vs v. Column sub-ranges via pointer
    // offsets (Nc is only the C stride).
    tgemm128<3><<<dim3(2, 200), 256>>>(px, qg_w,           qg_b,       pqg,       BN_TOT, 512, 256);
    tgemm128<1><<<dim3(2, 200), 256>>>(px, qg_w + 256*256, qg_b + 256, pqg + 256, BN_TOT, 512, 256);
    tgemm128<3><<<dim3(2, 200), 256>>>(px, kv_w,           kv_b,       pkv,       BN_TOT, 512, 256);
    tgemm128<1><<<dim3(2, 200), 256>>>(px, kv_w + 256*256, kv_b + 256, pkv + 256, BN_TOT, 512, 256);

    k_attn<<<512, 512, ATTN_SMEM>>>(pos, scale, power);
    k_dwc5<<<512, 256, DWC5_SMEM>>>(dwc_w, dwc_b);

    // residual-stream GEMMs tolerate plain tf32 (~1e-4 rel err)
    tgemm128<1><<<dim3(2, 200), 256>>>(pfused, proj_w, proj_b, pa, BN_TOT, 256, 256);
    k_ln1<<<dim3(13, 64), 256>>>(src, ln1_w, ln1_b);

    k_se<<<64, 512>>>(src, se_w);

    tgemm128<1><<<dim3(8, 200), 256>>>(ps, pin_w, nullptr, py, BN_TOT, 1024, 256);
    k_dw3<<<dim3(16, 64), 256, DW3_SMEM>>>(dw_w);
    tgemm128<1><<<dim3(2, 200), 256>>>(ph, pout_w, nullptr, pf, BN_TOT, 256, 512);

    k_ln2<<<dim3(13, 64), 256>>>(out, ln2_w, ln2_b);
}

// round 9
// speedup vs baseline: 1.4130x; 1.0652x over previous
#include <cuda_runtime.h>
#include <math.h>
#include <stdint.h>
#include <stddef.h>

#define BSZ 64
#define CCH 256
#define NPIX 400
#define BN_TOT (BSZ*NPIX)   // 25600

// ---------------- scratch (static device globals; no allocation) ----------------
static __device__ float g_x[(size_t)BN_TOT*256];
static __device__ float g_qg[(size_t)BN_TOT*512];
static __device__ float g_kv[(size_t)BN_TOT*512];
static __device__ float g_attn[(size_t)BN_TOT*256];
static __device__ float g_fused[(size_t)BN_TOT*256];
static __device__ float g_a[(size_t)BN_TOT*256];
static __device__ float g_s[(size_t)BN_TOT*256];
static __device__ float g_y[(size_t)BN_TOT*1024];
static __device__ float g_h[(size_t)BN_TOT*512];
static __device__ float g_f[(size_t)BN_TOT*256];
static __device__ float g_se[BSZ*512];

// ---------------- transpose src (B,C,N) -> x (BN,C) ----------------
__global__ __launch_bounds__(256) void k_transpose(const float* __restrict__ src) {
    __shared__ float sm[32][257];
    int b = blockIdx.y, n0 = blockIdx.x * 32;
    int tid = threadIdx.x;
    for (int j = tid; j < 8192; j += 256) {
        int c = j >> 5, i = j & 31;
        if (n0 + i < NPIX) sm[i][c] = src[(size_t)b*CCH*NPIX + (size_t)c*NPIX + n0 + i];
    }
    __syncthreads();
    for (int j = tid; j < 8192; j += 256) {
        int i = j >> 8, c = j & 255;
        int n = n0 + i;
        if (n < NPIX) g_x[((size_t)(b*NPIX + n))*256 + c] = sm[i][c];
    }
}

// ---------------- tf32 helpers ----------------
__device__ __forceinline__ unsigned f2tf(float x) {
    unsigned r;
    asm("cvt.rna.tf32.f32 %0, %1;" : "=r"(r) : "f"(x));
    return r;
}

#define MMA_TF32(d, a0,a1,a2,a3, b0,b1) \
    asm volatile("mma.sync.aligned.m16n8k8.row.col.f32.tf32.tf32.f32 " \
        "{%0,%1,%2,%3},{%4,%5,%6,%7},{%8,%9},{%0,%1,%2,%3};" \
        : "+f"(d[0]), "+f"(d[1]), "+f"(d[2]), "+f"(d[3]) \
        : "r"(a0), "r"(a1), "r"(a2), "r"(a3), "r"(b0), "r"(b1))

// ---------------- tensor-core GEMM (plain tf32): C = A @ W^T + bias -----------------
// Measured (R8): LN washout makes plain tf32 safe everywhere (rel_err stays ~1e-5..1e-4).
// M%128==0, K%16==0, grid.x covers the column range; Nc is ONLY the C row stride.
// Block 128x128, 8 warps of 64x32, k-step 16, double-buffered smem, stride-20 pad.
// __launch_bounds__(256,2): cap 128 regs -> 2 CTAs/SM (fixes occ=12.4% from R8).
#define TSTR 20
template<int SPLIT>
__global__ __launch_bounds__(256,2) void tgemm128(
        const float* __restrict__ A, const float* __restrict__ W,
        const float* __restrict__ bias, float* __restrict__ C,
        int M, int Nc, int K) {
    __shared__ float As[2][128*TSTR];
    __shared__ float Ws[2][128*TSTR];
    const int tid = threadIdx.x;
    const int bm = blockIdx.y * 128, bn = blockIdx.x * 128;
    const int warp = tid >> 5, lane = tid & 31;
    const int wm = (warp & 1) * 64;     // warp M offset within tile
    const int wn = (warp >> 1) * 32;    // warp N offset within tile
    const int gr = lane >> 2, gc = lane & 3;

    const int lr = tid >> 1;            // 0..127
    const int lc = (tid & 1) * 8;       // 0 or 8
    const float* Ap = A + (size_t)(bm + lr)*K + lc;
    const float* Wp = W + (size_t)(bn + lr)*K + lc;

    float acc[4][4][4];
    #pragma unroll
    for (int mt = 0; mt < 4; mt++)
        #pragma unroll
        for (int nt = 0; nt < 4; nt++)
            #pragma unroll
            for (int e = 0; e < 4; e++) acc[mt][nt][e] = 0.f;

    // preload tile 0
    float4 a0v = *(const float4*)(Ap);
    float4 a1v = *(const float4*)(Ap + 4);
    float4 w0v = *(const float4*)(Wp);
    float4 w1v = *(const float4*)(Wp + 4);
    *(float4*)(&As[0][lr*TSTR + lc])     = a0v;
    *(float4*)(&As[0][lr*TSTR + lc + 4]) = a1v;
    *(float4*)(&Ws[0][lr*TSTR + lc])     = w0v;
    *(float4*)(&Ws[0][lr*TSTR + lc + 4]) = w1v;
    __syncthreads();

    int buf = 0;
    for (int k0 = 0; k0 < K; k0 += 16) {
        const bool more = (k0 + 16) < K;
        if (more) {
            a0v = *(const float4*)(Ap + k0 + 16);
            a1v = *(const float4*)(Ap + k0 + 20);
            w0v = *(const float4*)(Wp + k0 + 16);
            w1v = *(const float4*)(Wp + k0 + 20);
        }
        const float* as = As[buf];
        const float* ws = Ws[buf];
        #pragma unroll
        for (int s = 0; s < 16; s += 8) {
            unsigned bh[4][2];
            #pragma unroll
            for (int nt = 0; nt < 4; nt++) {
                int nrow = wn + nt*8 + gr;
                bh[nt][0] = f2tf(ws[nrow*TSTR + s + gc]);
                bh[nt][1] = f2tf(ws[nrow*TSTR + s + gc + 4]);
            }
            #pragma unroll
            for (int mt = 0; mt < 4; mt++) {
                int r0 = wm + mt*16 + gr;
                int r1 = r0 + 8;
                unsigned ah0 = f2tf(as[r0*TSTR + s + gc]);
                unsigned ah1 = f2tf(as[r1*TSTR + s + gc]);
                unsigned ah2 = f2tf(as[r0*TSTR + s + gc + 4]);
                unsigned ah3 = f2tf(as[r1*TSTR + s + gc + 4]);
                #pragma unroll
                for (int nt = 0; nt < 4; nt++)
                    MMA_TF32(acc[mt][nt], ah0, ah1, ah2, ah3, bh[nt][0], bh[nt][1]);
            }
        }
        if (more) {
            int nb = buf ^ 1;
            *(float4*)(&As[nb][lr*TSTR + lc])     = a0v;
            *(float4*)(&As[nb][lr*TSTR + lc + 4]) = a1v;
            *(float4*)(&Ws[nb][lr*TSTR + lc])     = w0v;
            *(float4*)(&Ws[nb][lr*TSTR + lc + 4]) = w1v;
            __syncthreads();
            buf = nb;
        }
    }

    #pragma unroll
    for (int nt = 0; nt < 4; nt++) {
        int col = bn + wn + nt*8 + gc*2;
        float b0 = bias ? bias[col]     : 0.f;
        float b1 = bias ? bias[col + 1] : 0.f;
        #pragma unroll
        for (int mt = 0; mt < 4; mt++) {
            int row = bm + wm + mt*16 + gr;
            float2 v0 = make_float2(acc[mt][nt][0] + b0, acc[mt][nt][1] + b1);
            float2 v1 = make_float2(acc[mt][nt][2] + b0, acc[mt][nt][3] + b1);
            *(float2*)(&C[(size_t)row*Nc + col])       = v0;
            *(float2*)(&C[(size_t)(row + 8)*Nc + col]) = v1;
        }
    }
}

// ---------------- linear polarity attention, one block per (b, head) ----------------
// Polarity trick: for any x exactly one of relu(x)^p, relu(-x)^p is nonzero.
// Store a SIGNED magnitude ks = copysign(|k|^p, k); k_pos=max(ks,0), k_neg=max(-ks,0).
// Halves MUFU work AND halves smem (111KB -> 2 CTAs/SM, occupancy 2x).
// dyn smem: ks[400*32] vv[400*32] kvs[2*64*16] km[64] scl[32] pwl[32] = 27776 floats
#define ATTN_SMEM (27776*4)
__global__ __launch_bounds__(512,2) void k_attn(const float* __restrict__ pos,
        const float* __restrict__ scale, const float* __restrict__ power) {
    int b = blockIdx.x >> 3, h = blockIdx.x & 7;
    extern __shared__ float sm[];
    float* ks  = sm;             // [n][32]  signed |k|^p
    float* vv  = sm + 12800;     // [n][32]  concat(v1, v2) per head
    float* kvs = sm + 25600;     // [branch][64][16]
    float* km  = sm + 27648;     // [64]
    float* scl = sm + 27712;     // [32]
    float* pwl = sm + 27744;     // [32]
    int tid = threadIdx.x;
    if (tid < 32) {
        scl[tid] = logf(1.f + expf(scale[h*32 + tid]));
        pwl[tid] = 1.f + 4.f / (1.f + expf(-power[h*32 + tid]));
    }
    __syncthreads();

    // Phase A: signed magnitudes (one powf per (n,dd))
    for (int i = tid; i < 400*32; i += 512) {
        int n = i >> 5, dd = i & 31;
        float kraw = (g_kv[((size_t)(b*400 + n))*512 + h*32 + dd] + pos[n*256 + h*32 + dd]) / scl[dd];
        float av = fabsf(kraw);
        float pw = (av > 0.f) ? __powf(fmaxf(av, 1e-30f), pwl[dd]) : 0.f;
        ks[i] = (kraw > 0.f) ? pw : ((kraw < 0.f) ? -pw : 0.f);
    }
    for (int i = tid; i < 400*32; i += 512) {
        int n = i >> 5, e = i & 31;
        int c = (e < 16) ? (256 + h*16 + e) : (384 + h*16 + (e - 16));
        vv[i] = g_kv[((size_t)(b*400 + n))*512 + c];
    }
    __syncthreads();

    // Phase B: k_mean (threads 0..63); d<32 -> k_pos row, d>=32 -> k_neg row
    if (tid < 64) {
        int dd = tid & 31; bool pos_row = tid < 32;
        float s = 0.f;
        for (int n = 0; n < 400; n++) {
            float v = ks[n*32 + dd];
            s += pos_row ? fmaxf(v, 0.f) : fmaxf(-v, 0.f);
        }
        km[tid] = s * (1.f/400.f);
    }
    // Phase C: kv matrices (each thread 4 outputs: fixed d, branch, 4 e's)
    {
        int d = tid & 63, grp = tid >> 6, br = grp >> 2, e0 = (grp & 3) * 4;
        int dd = d & 31; bool pos_row = d < 32;
        float a0 = 0, a1 = 0, a2 = 0, a3 = 0;
        const float* vb = vv + br*16 + e0;
        #pragma unroll 4
        for (int n = 0; n < 400; n++) {
            float v = ks[n*32 + dd];
            float kcv = pos_row ? fmaxf(v, 0.f) : fmaxf(-v, 0.f);
            const float* vp = vb + n*32;
            a0 += kcv * vp[0]; a1 += kcv * vp[1];
            a2 += kcv * vp[2]; a3 += kcv * vp[3];
        }
        const float inv = 1.f/400.f;
        float* o = kvs + br*1024 + d*16 + e0;
        o[0] = a0*inv; o[1] = a1*inv; o[2] = a2*inv; o[3] = a3*inv;
    }
    __syncthreads();

    // Phase D: per-token output (one powf per dd; operand selected by sign)
    for (int n = tid; n < 400; n += 512) {
        float os[16], oo[16];
        #pragma unroll
        for (int e = 0; e < 16; e++) { os[e] = 0.f; oo[e] = 0.f; }
        float ss = 0.f, so = 0.f;
        const float* qrow = g_qg + ((size_t)(b*400 + n))*512 + h*32;
        #pragma unroll 2
        for (int dd = 0; dd < 32; dd++) {
            float q = qrow[dd] / scl[dd];
            float aq = fabsf(q);
            float pw = (aq > 0.f) ? __powf(fmaxf(aq, 1e-30f), pwl[dd]) : 0.f;
            bool posq = (q > 0.f);
            ss += pw * (posq ? km[dd] : km[32 + dd]);
            so += pw * (posq ? km[32 + dd] : km[dd]);
            const float4* sp = (const float4*)(kvs + (posq ? dd : 32 + dd)*16);
            const float4* op = (const float4*)(kvs + 1024 + (posq ? 32 + dd : dd)*16);
            #pragma unroll
            for (int e4 = 0; e4 < 4; e4++) {
                float4 aa = sp[e4], cc = op[e4];
                os[e4*4+0] += pw*aa.x; os[e4*4+1] += pw*aa.y;
                os[e4*4+2] += pw*aa.z; os[e4*4+3] += pw*aa.w;
                oo[e4*4+0] += pw*cc.x; oo[e4*4+1] += pw*cc.y;
                oo[e4*4+2] += pw*cc.z; oo[e4*4+3] += pw*cc.w;
            }
        }
        float zs = 1.f/(ss + 1e-6f), zo = 1.f/(so + 1e-6f);
        float* outp = g_attn + ((size_t)(b*400 + n))*256 + h*32;
        #pragma unroll
        for (int e = 0; e < 16; e++) { outp[e] = os[e]*zs; outp[16 + e] = oo[e]*zo; }
    }
}

// ---------------- 5x5 depthwise conv on v (FLAT reshape mapping!) + (attn+vd)*g ----------------
// F = n*256+c  <->  (bh = F/12800, y, x, d) with F = bh*12800 + y*640 + x*32 + d.
#define DWC5_SMEM ((18432 + 800 + 32)*4)
__global__ __launch_bounds__(256) void k_dwc5(const float* __restrict__ w, const float* __restrict__ bias) {
    int b = blockIdx.x >> 3, bh = blockIdx.x & 7;
    extern __shared__ float sm[];
    float* tile = sm;          // [24*24][32]
    float* ws   = sm + 18432;  // [32][25]
    float* wb   = sm + 19232;  // [32]
    int tid = threadIdx.x;
    for (int i = tid; i < 800; i += 256) ws[i] = w[i];
    if (tid < 32) wb[tid] = bias[tid];
    for (int i = tid; i < 576*32; i += 256) {
        int pos = i >> 5, d = i & 31;
        int y = pos / 24 - 2, x = pos % 24 - 2;
        float v = 0.f;
        if (y >= 0 && y < 20 && x >= 0 && x < 20) {
            int F = bh*12800 + y*640 + x*32 + d;
            int n = F >> 8, c = F & 255;
            v = g_kv[((size_t)(b*400 + n))*512 + 256 + c];
        }
        tile[i] = v;
    }
    __syncthreads();
    for (int i = tid; i < 400*32; i += 256) {
        int pos = i >> 5, d = i & 31;
        int y = pos / 20, x = pos % 20;
        float acc = wb[d];
        #pragma unroll
        for (int ky = 0; ky < 5; ky++)
            #pragma unroll
            for (int kx = 0; kx < 5; kx++)
                acc += ws[d*25 + ky*5 + kx] * tile[((y + ky)*24 + (x + kx))*32 + d];
        int F = bh*12800 + y*640 + x*32 + d;
        int n = F >> 8, c = F & 255;
        size_t bn = (size_t)(b*400 + n);
        g_fused[bn*256 + c] = (g_attn[bn*256 + c] + acc) * g_qg[bn*512 + 256 + c];
    }
}

// ---------------- channel LayerNorm 1: s = LN(src + a), output (BN, C) ----------------
__global__ __launch_bounds__(256) void k_ln1(const float* __restrict__ src,
        const float* __restrict__ w, const float* __restrict__ bias) {
    __shared__ float sm[32][257];
    __shared__ float smean[32], srs[32];
    int b = blockIdx.y, n0 = blockIdx.x * 32;
    int tid = threadIdx.x;
    for (int j = tid; j < 8192; j += 256) {
        int c = j >> 5, i = j & 31;
        if (n0 + i < 400) sm[i][c] = src[(size_t)b*102400 + c*400 + n0 + i];
    }
    __syncthreads();
    for (int j = tid; j < 8192; j += 256) {
        int i = j >> 8, c = j & 255;
        if (n0 + i < 400) sm[i][c] += g_a[((size_t)(b*400 + n0 + i))*256 + c];
    }
    __syncthreads();
    int warp = tid >> 5, lane = tid & 31;
    for (int i = warp; i < 32; i += 8) {
        if (n0 + i < 400) {
            float s1 = 0.f, s2 = 0.f;
            #pragma unroll
            for (int t = 0; t < 8; t++) { float v = sm[i][lane + t*32]; s1 += v; s2 += v*v; }
            #pragma unroll
            for (int off = 16; off > 0; off >>= 1) {
                s1 += __shfl_xor_sync(0xffffffffu, s1, off);
                s2 += __shfl_xor_sync(0xffffffffu, s2, off);
            }
            if (lane == 0) {
                float mu = s1 * (1.f/256.f);
                float var = s2 * (1.f/256.f) - mu*mu;
                smean[i] = mu; srs[i] = rsqrtf(var + 1e-6f);
            }
        }
    }
    __syncthreads();
    for (int j = tid; j < 8192; j += 256) {
        int i = j >> 8, c = j & 255;
        int n = n0 + i;
        if (n < 400)
            g_s[((size_t)(b*400 + n))*256 + c] = w[c]*(sm[i][c] - smean[i])*srs[i] + bias[c];
    }
}

// ---------------- SE gate (merged): mean over src spatial, then sigmoid(se_w . mean) ----------------
__global__ __launch_bounds__(512) void k_se(const float* __restrict__ src,
        const float* __restrict__ sew) {
    __shared__ float m[256];
    int b = blockIdx.x, tid = threadIdx.x;
    int warp = tid >> 5, lane = tid & 31;
    for (int c = warp; c < 256; c += 16) {
        float s = 0.f;
        for (int n = lane; n < 400; n += 32) s += src[(size_t)b*102400 + c*400 + n];
        #pragma unroll
        for (int off = 16; off > 0; off >>= 1) s += __shfl_xor_sync(0xffffffffu, s, off);
        if (lane == 0) m[c] = s * (1.f/400.f);
    }
    __syncthreads();
    float s = 0.f;
    const float* wr = sew + (size_t)tid*256;
    #pragma unroll 4
    for (int c = 0; c < 256; c++) s += wr[c]*m[c];
    g_se[b*512 + tid] = 1.f/(1.f + expf(-s));
}

// ---------------- 3x3 depthwise + exact GELU gate + SE ----------------
#define DW3_SMEM ((15488*2 + 288*2)*4)
__global__ __launch_bounds__(256) void k_dw3(const float* __restrict__ w) {
    int b = blockIdx.y, jt = blockIdx.x;  // jt in [0,16): tile of 32 channels
    extern __shared__ float sm[];
    float* t1 = sm;                 // [22*22][32] x1 half
    float* t2 = sm + 15488;         // [22*22][32] x2 half
    float* w1 = sm + 30976;         // [32][9]
    float* w2 = sm + 31264;         // [32][9]
    int tid = threadIdx.x;
    for (int i = tid; i < 288; i += 256) {
        int jj = i / 9, t = i % 9;
        w1[i] = w[(jt*32 + jj)*9 + t];
        w2[i] = w[(512 + jt*32 + jj)*9 + t];
    }
    for (int i = tid; i < 484*32; i += 256) {
        int pos = i >> 5, jj = i & 31;
        int y = pos / 22 - 1, x = pos % 22 - 1;
        float v1 = 0.f, v2 = 0.f;
        if (y >= 0 && y < 20 && x >= 0 && x < 20) {
            size_t base = ((size_t)(b*400 + y*20 + x))*1024 + jt*32 + jj;
            v1 = g_y[base]; v2 = g_y[base + 512];
        }
        t1[i] = v1; t2[i] = v2;
    }
    __syncthreads();
    for (int i = tid; i < 400*32; i += 256) {
        int pos = i >> 5, jj = i & 31;
        int y = pos / 20, x = pos % 20;
        float d1 = 0.f, d2 = 0.f;
        #pragma unroll
        for (int ky = 0; ky < 3; ky++)
            #pragma unroll
            for (int kx = 0; kx < 3; kx++) {
                int tp = ((y + ky)*22 + (x + kx))*32 + jj;
                d1 += w1[jj*9 + ky*3 + kx] * t1[tp];
                d2 += w2[jj*9 + ky*3 + kx] * t2[tp];
            }
        float ge = 0.5f * d1 * (1.f + erff(d1 * 0.70710678118654752f));
        g_h[((size_t)(b*400 + pos))*512 + jt*32 + jj] = ge * d2 * g_se[b*512 + jt*32 + jj];
    }
}

// ---------------- LN2: out = LN(s + f), output NCHW (B,C,N) ----------------
__global__ __launch_bounds__(256) void k_ln2(float* __restrict__ out,
        const float* __restrict__ w, const float* __restrict__ bias) {
    __shared__ float sm[32][257];
    __shared__ float smean[32], srs[32];
    int b = blockIdx.y, n0 = blockIdx.x * 32;
    int tid = threadIdx.x;
    for (int j = tid; j < 8192; j += 256) {
        int i = j >> 8, c = j & 255;
        int n = n0 + i;
        if (n < 400) {
            size_t bn = (size_t)(b*400 + n);
            sm[i][c] = g_s[bn*256 + c] + g_f[bn*256 + c];
        }
    }
    __syncthreads();
    int warp = tid >> 5, lane = tid & 31;
    for (int i = warp; i < 32; i += 8) {
        if (n0 + i < 400) {
            float s1 = 0.f, s2 = 0.f;
            #pragma unroll
            for (int t = 0; t < 8; t++) { float v = sm[i][lane + t*32]; s1 += v; s2 += v*v; }
            #pragma unroll
            for (int off = 16; off > 0; off >>= 1) {
                s1 += __shfl_xor_sync(0xffffffffu, s1, off);
                s2 += __shfl_xor_sync(0xffffffffu, s2, off);
            }
            if (lane == 0) {
                float mu = s1 * (1.f/256.f);
                float var = s2 * (1.f/256.f) - mu*mu;
                smean[i] = mu; srs[i] = rsqrtf(var + 1e-6f);
            }
        }
    }
    __syncthreads();
    for (int j = tid; j < 8192; j += 256) {
        int c = j >> 5, i = j & 31;
        int n = n0 + i;
        if (n < 400)
            out[(size_t)b*102400 + c*400 + n] = w[c]*(sm[i][c] - smean[i])*srs[i] + bias[c];
    }
}

// ---------------- host launch ----------------
extern "C" void kernel_launch(void* const* d_in, const int* in_sizes, int n_in,
                              void* d_out, int out_size) {
    const float* src    = (const float*)d_in[0];
    const float* qg_w   = (const float*)d_in[1];
    const float* qg_b   = (const float*)d_in[2];
    const float* kv_w   = (const float*)d_in[3];
    const float* kv_b   = (const float*)d_in[4];
    const float* proj_w = (const float*)d_in[5];
    const float* proj_b = (const float*)d_in[6];
    const float* dwc_w  = (const float*)d_in[7];
    const float* dwc_b  = (const float*)d_in[8];
    const float* power  = (const float*)d_in[9];
    const float* scale  = (const float*)d_in[10];
    const float* pos    = (const float*)d_in[11];
    const float* pin_w  = (const float*)d_in[12];
    const float* dw_w   = (const float*)d_in[13];
    const float* se_w   = (const float*)d_in[14];
    const float* pout_w = (const float*)d_in[15];
    const float* ln1_w  = (const float*)d_in[16];
    const float* ln1_b  = (const float*)d_in[17];
    const float* ln2_w  = (const float*)d_in[18];
    const float* ln2_b  = (const float*)d_in[19];
    float* out = (float*)d_out;

    float *px, *pqg, *pkv, *pfused, *pa, *ps, *py, *ph, *pf;
    cudaGetSymbolAddress((void**)&px, g_x);
    cudaGetSymbolAddress((void**)&pqg, g_qg);
    cudaGetSymbolAddress((void**)&pkv, g_kv);
    cudaGetSymbolAddress((void**)&pfused, g_fused);
    cudaGetSymbolAddress((void**)&pa, g_a);
    cudaGetSymbolAddress((void**)&ps, g_s);
    cudaGetSymbolAddress((void**)&py, g_y);
    cudaGetSymbolAddress((void**)&ph, g_h);
    cudaGetSymbolAddress((void**)&pf, g_f);

    cudaFuncSetAttribute(k_attn, cudaFuncAttributeMaxDynamicSharedMemorySize, ATTN_SMEM);
    cudaFuncSetAttribute(k_dwc5, cudaFuncAttributeMaxDynamicSharedMemorySize, DWC5_SMEM);
    cudaFuncSetAttribute(k_dw3,  cudaFuncAttributeMaxDynamicSharedMemorySize, DW3_SMEM);

    k_transpose<<<dim3(13, 64), 256>>>(src);

    // All GEMMs plain tf32 (R8 measured washout: rel_err stayed 4e-6 with
    // residual GEMMs at split-1; spend the headroom).
    tgemm128<1><<<dim3(4, 200), 256>>>(px, qg_w, qg_b, pqg, BN_TOT, 512, 256);
    tgemm128<1><<<dim3(4, 200), 256>>>(px, kv_w, kv_b, pkv, BN_TOT, 512, 256);

    k_attn<<<512, 512, ATTN_SMEM>>>(pos, scale, power);
    k_dwc5<<<512, 256, DWC5_SMEM>>>(dwc_w, dwc_b);

    tgemm128<1><<<dim3(2, 200), 256>>>(pfused, proj_w, proj_b, pa, BN_TOT, 256, 256);
    k_ln1<<<dim3(13, 64), 256>>>(src, ln1_w, ln1_b);

    k_se<<<64, 512>>>(src, se_w);

    tgemm128<1><<<dim3(8, 200), 256>>>(ps, pin_w, nullptr, py, BN_TOT, 1024, 256);
    k_dw3<<<dim3(16, 64), 256, DW3_SMEM>>>(dw_w);
    tgemm128<1><<<dim3(2, 200), 256>>>(ph, pout_w, nullptr, pf, BN_TOT, 256, 512);

    k_ln2<<<dim3(13, 64), 256>>>(out, ln2_w, ln2_b);
}

// round 12
// speedup vs baseline: 1.4373x; 1.0172x over previous
#include <cuda_runtime.h>
#include <math.h>
#include <stdint.h>
#include <stddef.h>

#define BSZ 64
#define CCH 256
#define NPIX 400
#define BN_TOT (BSZ*NPIX)   // 25600

// ---------------- scratch (static device globals; no allocation) ----------------
static __device__ float g_x[(size_t)BN_TOT*256];
static __device__ float g_qg[(size_t)BN_TOT*512];
static __device__ float g_kv[(size_t)BN_TOT*512];
static __device__ float g_attn[(size_t)BN_TOT*256];
static __device__ float g_fused[(size_t)BN_TOT*256];
static __device__ float g_a[(size_t)BN_TOT*256];
static __device__ float g_s[(size_t)BN_TOT*256];
static __device__ float g_y[(size_t)BN_TOT*1024];
static __device__ float g_h[(size_t)BN_TOT*512];
static __device__ float g_f[(size_t)BN_TOT*256];
static __device__ float g_se[BSZ*512];

// ---------------- transpose src (B,C,N) -> x (BN,C) ----------------
__global__ __launch_bounds__(256) void k_transpose(const float* __restrict__ src) {
    __shared__ float sm[32][257];
    int b = blockIdx.y, n0 = blockIdx.x * 32;
    int tid = threadIdx.x;
    for (int j = tid; j < 8192; j += 256) {
        int c = j >> 5, i = j & 31;
        if (n0 + i < NPIX) sm[i][c] = src[(size_t)b*CCH*NPIX + (size_t)c*NPIX + n0 + i];
    }
    __syncthreads();
    for (int j = tid; j < 8192; j += 256) {
        int i = j >> 8, c = j & 255;
        int n = n0 + i;
        if (n < NPIX) g_x[((size_t)(b*NPIX + n))*256 + c] = sm[i][c];
    }
}

// ---------------- tf32 helpers ----------------
__device__ __forceinline__ unsigned f2tf(float x) {
    unsigned r;
    asm("cvt.rna.tf32.f32 %0, %1;" : "=r"(r) : "f"(x));
    return r;
}

#define MMA_TF32(d, a0,a1,a2,a3, b0,b1) \
    asm volatile("mma.sync.aligned.m16n8k8.row.col.f32.tf32.tf32.f32 " \
        "{%0,%1,%2,%3},{%4,%5,%6,%7},{%8,%9},{%0,%1,%2,%3};" \
        : "+f"(d[0]), "+f"(d[1]), "+f"(d[2]), "+f"(d[3]) \
        : "r"(a0), "r"(a1), "r"(a2), "r"(a3), "r"(b0), "r"(b1))

// ---------------- tensor-core GEMM (plain tf32): C = A @ W^T + bias -----------------
// tf32 conversion hoisted to the smem STORE (R8 profile: alu=25% from in-loop cvt,
// each A element converted 4x by the 4 warps sharing its row range). smem holds
// tf32 bit patterns; inner loop is pure LDS+MMA. Numerically identical.
// M%128==0, K%16==0; Nc is ONLY the C row stride. Block 128x128, 8 warps of
// 64x32, k-step 16, double-buffered, stride-20 pad (20%4==0 keeps uint4 stores aligned).
#define TSTR 20
__global__ __launch_bounds__(256,2) void tgemm128(
        const float* __restrict__ A, const float* __restrict__ W,
        const float* __restrict__ bias, float* __restrict__ C,
        int M, int Nc, int K) {
    __shared__ unsigned As[2][128*TSTR];
    __shared__ unsigned Ws[2][128*TSTR];
    const int tid = threadIdx.x;
    const int bm = blockIdx.y * 128, bn = blockIdx.x * 128;
    const int warp = tid >> 5, lane = tid & 31;
    const int wm = (warp & 1) * 64;     // warp M offset within tile
    const int wn = (warp >> 1) * 32;    // warp N offset within tile
    const int gr = lane >> 2, gc = lane & 3;

    const int lr = tid >> 1;            // 0..127
    const int lc = (tid & 1) * 8;       // 0 or 8
    const float* Ap = A + (size_t)(bm + lr)*K + lc;
    const float* Wp = W + (size_t)(bn + lr)*K + lc;

    float acc[4][4][4];
    #pragma unroll
    for (int mt = 0; mt < 4; mt++)
        #pragma unroll
        for (int nt = 0; nt < 4; nt++)
            #pragma unroll
            for (int e = 0; e < 4; e++) acc[mt][nt][e] = 0.f;

    // convert a float4 pair to tf32 bits and store as uint4
    auto store_tile = [&](unsigned* dst, float4 v0, float4 v1) {
        uint4 u0 = make_uint4(f2tf(v0.x), f2tf(v0.y), f2tf(v0.z), f2tf(v0.w));
        uint4 u1 = make_uint4(f2tf(v1.x), f2tf(v1.y), f2tf(v1.z), f2tf(v1.w));
        *(uint4*)(dst)     = u0;
        *(uint4*)(dst + 4) = u1;
    };

    // preload tile 0
    float4 a0v = *(const float4*)(Ap);
    float4 a1v = *(const float4*)(Ap + 4);
    float4 w0v = *(const float4*)(Wp);
    float4 w1v = *(const float4*)(Wp + 4);
    store_tile(&As[0][lr*TSTR + lc], a0v, a1v);
    store_tile(&Ws[0][lr*TSTR + lc], w0v, w1v);
    __syncthreads();

    int buf = 0;
    for (int k0 = 0; k0 < K; k0 += 16) {
        const bool more = (k0 + 16) < K;
        if (more) {
            a0v = *(const float4*)(Ap + k0 + 16);
            a1v = *(const float4*)(Ap + k0 + 20);
            w0v = *(const float4*)(Wp + k0 + 16);
            w1v = *(const float4*)(Wp + k0 + 20);
        }
        const unsigned* as = As[buf];
        const unsigned* ws = Ws[buf];
        #pragma unroll
        for (int s = 0; s < 16; s += 8) {
            unsigned bh[4][2];
            #pragma unroll
            for (int nt = 0; nt < 4; nt++) {
                int nrow = wn + nt*8 + gr;
                bh[nt][0] = ws[nrow*TSTR + s + gc];
                bh[nt][1] = ws[nrow*TSTR + s + gc + 4];
            }
            #pragma unroll
            for (int mt = 0; mt < 4; mt++) {
                int r0 = wm + mt*16 + gr;
                int r1 = r0 + 8;
                unsigned ah0 = as[r0*TSTR + s + gc];
                unsigned ah1 = as[r1*TSTR + s + gc];
                unsigned ah2 = as[r0*TSTR + s + gc + 4];
                unsigned ah3 = as[r1*TSTR + s + gc + 4];
                #pragma unroll
                for (int nt = 0; nt < 4; nt++)
                    MMA_TF32(acc[mt][nt], ah0, ah1, ah2, ah3, bh[nt][0], bh[nt][1]);
            }
        }
        if (more) {
            int nb = buf ^ 1;
            store_tile(&As[nb][lr*TSTR + lc], a0v, a1v);
            store_tile(&Ws[nb][lr*TSTR + lc], w0v, w1v);
            __syncthreads();
            buf = nb;
        }
    }

    #pragma unroll
    for (int nt = 0; nt < 4; nt++) {
        int col = bn + wn + nt*8 + gc*2;
        float b0 = bias ? bias[col]     : 0.f;
        float b1 = bias ? bias[col + 1] : 0.f;
        #pragma unroll
        for (int mt = 0; mt < 4; mt++) {
            int row = bm + wm + mt*16 + gr;
            float2 v0 = make_float2(acc[mt][nt][0] + b0, acc[mt][nt][1] + b1);
            float2 v1 = make_float2(acc[mt][nt][2] + b0, acc[mt][nt][3] + b1);
            *(float2*)(&C[(size_t)row*Nc + col])       = v0;
            *(float2*)(&C[(size_t)(row + 8)*Nc + col]) = v1;
        }
    }
}

// ---------------- linear polarity attention, one block per (b, head) ----------------
// Polarity trick + signed-magnitude smem (111KB -> 2 CTAs/SM).
// Phase C: one LDS.128 for the 4 v values. rscl = 1/softplus (mul, not div).
// Phase D: q row loaded as 8x LDG.128.
// dyn smem: ks[400*32] vv[400*32] kvs[2*64*16] km[64] rscl[32] pwl[32] = 27776 floats
#define ATTN_SMEM (27776*4)
__global__ __launch_bounds__(512,2) void k_attn(const float* __restrict__ pos,
        const float* __restrict__ scale, const float* __restrict__ power) {
    int b = blockIdx.x >> 3, h = blockIdx.x & 7;
    extern __shared__ float sm[];
    float* ks   = sm;             // [n][32]  signed |k|^p
    float* vv   = sm + 12800;     // [n][32]  concat(v1, v2) per head
    float* kvs  = sm + 25600;     // [branch][64][16]
    float* km   = sm + 27648;     // [64]
    float* rscl = sm + 27712;     // [32] reciprocal of softplus(scale)
    float* pwl  = sm + 27744;     // [32]
    int tid = threadIdx.x;
    if (tid < 32) {
        rscl[tid] = 1.f / logf(1.f + expf(scale[h*32 + tid]));
        pwl[tid]  = 1.f + 4.f / (1.f + expf(-power[h*32 + tid]));
    }
    __syncthreads();

    // Phase A: signed magnitudes (one powf per (n,dd))
    for (int i = tid; i < 400*32; i += 512) {
        int n = i >> 5, dd = i & 31;
        float kraw = (g_kv[((size_t)(b*400 + n))*512 + h*32 + dd] + pos[n*256 + h*32 + dd]) * rscl[dd];
        float av = fabsf(kraw);
        float pw = (av > 0.f) ? __powf(fmaxf(av, 1e-30f), pwl[dd]) : 0.f;
        ks[i] = (kraw > 0.f) ? pw : ((kraw < 0.f) ? -pw : 0.f);
    }
    for (int i = tid; i < 400*32; i += 512) {
        int n = i >> 5, e = i & 31;
        int c = (e < 16) ? (256 + h*16 + e) : (384 + h*16 + (e - 16));
        vv[i] = g_kv[((size_t)(b*400 + n))*512 + c];
    }
    __syncthreads();

    // Phase B: k_mean (threads 0..63); d<32 -> k_pos row, d>=32 -> k_neg row
    if (tid < 64) {
        int dd = tid & 31; bool pos_row = tid < 32;
        float s = 0.f;
        for (int n = 0; n < 400; n++) {
            float v = ks[n*32 + dd];
            s += pos_row ? fmaxf(v, 0.f) : fmaxf(-v, 0.f);
        }
        km[tid] = s * (1.f/400.f);
    }
    // Phase C: kv matrices (each thread 4 outputs: fixed d, branch, 4 e's)
    {
        int d = tid & 63, grp = tid >> 6, br = grp >> 2, e0 = (grp & 3) * 4;
        int dd = d & 31; bool pos_row = d < 32;
        float a0 = 0, a1 = 0, a2 = 0, a3 = 0;
        const float* vb = vv + br*16 + e0;   // 16B-aligned (e0 multiple of 4)
        #pragma unroll 4
        for (int n = 0; n < 400; n++) {
            float v = ks[n*32 + dd];
            float kcv = pos_row ? fmaxf(v, 0.f) : fmaxf(-v, 0.f);
            float4 vq = *(const float4*)(vb + n*32);   // one LDS.128
            a0 += kcv * vq.x; a1 += kcv * vq.y;
            a2 += kcv * vq.z; a3 += kcv * vq.w;
        }
        const float inv = 1.f/400.f;
        float* o = kvs + br*1024 + d*16 + e0;
        o[0] = a0*inv; o[1] = a1*inv; o[2] = a2*inv; o[3] = a3*inv;
    }
    __syncthreads();

    // Phase D: per-token output (one powf per dd; operand selected by sign)
    for (int n = tid; n < 400; n += 512) {
        float os[16], oo[16];
        #pragma unroll
        for (int e = 0; e < 16; e++) { os[e] = 0.f; oo[e] = 0.f; }
        float ss = 0.f, so = 0.f;
        const float* qrow = g_qg + ((size_t)(b*400 + n))*512 + h*32;
        float qbuf[32];
        #pragma unroll
        for (int v4 = 0; v4 < 8; v4++)
            *(float4*)(qbuf + v4*4) = *(const float4*)(qrow + v4*4);  // LDG.128
        #pragma unroll 2
        for (int dd = 0; dd < 32; dd++) {
            float q = qbuf[dd] * rscl[dd];
            float aq = fabsf(q);
            float pw = (aq > 0.f) ? __powf(fmaxf(aq, 1e-30f), pwl[dd]) : 0.f;
            bool posq = (q > 0.f);
            ss += pw * (posq ? km[dd] : km[32 + dd]);
            so += pw * (posq ? km[32 + dd] : km[dd]);
            const float4* sp = (const float4*)(kvs + (posq ? dd : 32 + dd)*16);
            const float4* op = (const float4*)(kvs + 1024 + (posq ? 32 + dd : dd)*16);
            #pragma unroll
            for (int e4 = 0; e4 < 4; e4++) {
                float4 aa = sp[e4], cc = op[e4];
                os[e4*4+0] += pw*aa.x; os[e4*4+1] += pw*aa.y;
                os[e4*4+2] += pw*aa.z; os[e4*4+3] += pw*aa.w;
                oo[e4*4+0] += pw*cc.x; oo[e4*4+1] += pw*cc.y;
                oo[e4*4+2] += pw*cc.z; oo[e4*4+3] += pw*cc.w;
            }
        }
        float zs = 1.f/(ss + 1e-6f), zo = 1.f/(so + 1e-6f);
        float* outp = g_attn + ((size_t)(b*400 + n))*256 + h*32;
        #pragma unroll
        for (int e = 0; e < 16; e++) { outp[e] = os[e]*zs; outp[16 + e] = oo[e]*zo; }
    }
}

// ---------------- 5x5 depthwise conv on v (FLAT reshape mapping!) + (attn+vd)*g ----------------
// F = n*256+c  <->  (bh = F/12800, y, x, d) with F = bh*12800 + y*640 + x*32 + d.
#define DWC5_SMEM ((18432 + 800 + 32)*4)
__global__ __launch_bounds__(256) void k_dwc5(const float* __restrict__ w, const float* __restrict__ bias) {
    int b = blockIdx.x >> 3, bh = blockIdx.x & 7;
    extern __shared__ float sm[];
    float* tile = sm;          // [24*24][32]
    float* ws   = sm + 18432;  // [32][25]
    float* wb   = sm + 19232;  // [32]
    int tid = threadIdx.x;
    for (int i = tid; i < 800; i += 256) ws[i] = w[i];
    if (tid < 32) wb[tid] = bias[tid];
    for (int i = tid; i < 576*32; i += 256) {
        int pos = i >> 5, d = i & 31;
        int y = pos / 24 - 2, x = pos % 24 - 2;
        float v = 0.f;
        if (y >= 0 && y < 20 && x >= 0 && x < 20) {
            int F = bh*12800 + y*640 + x*32 + d;
            int n = F >> 8, c = F & 255;
            v = g_kv[((size_t)(b*400 + n))*512 + 256 + c];
        }
        tile[i] = v;
    }
    __syncthreads();
    for (int i = tid; i < 400*32; i += 256) {
        int pos = i >> 5, d = i & 31;
        int y = pos / 20, x = pos % 20;
        float acc = wb[d];
        #pragma unroll
        for (int ky = 0; ky < 5; ky++)
            #pragma unroll
            for (int kx = 0; kx < 5; kx++)
                acc += ws[d*25 + ky*5 + kx] * tile[((y + ky)*24 + (x + kx))*32 + d];
        int F = bh*12800 + y*640 + x*32 + d;
        int n = F >> 8, c = F & 255;
        size_t bn = (size_t)(b*400 + n);
        g_fused[bn*256 + c] = (g_attn[bn*256 + c] + acc) * g_qg[bn*512 + 256 + c];
    }
}

// ---------------- channel LayerNorm 1: s = LN(src + a), output (BN, C) ----------------
__global__ __launch_bounds__(256) void k_ln1(const float* __restrict__ src,
        const float* __restrict__ w, const float* __restrict__ bias) {
    __shared__ float sm[32][257];
    __shared__ float smean[32], srs[32];
    int b = blockIdx.y, n0 = blockIdx.x * 32;
    int tid = threadIdx.x;
    for (int j = tid; j < 8192; j += 256) {
        int c = j >> 5, i = j & 31;
        if (n0 + i < 400) sm[i][c] = src[(size_t)b*102400 + c*400 + n0 + i];
    }
    __syncthreads();
    for (int j = tid; j < 8192; j += 256) {
        int i = j >> 8, c = j & 255;
        if (n0 + i < 400) sm[i][c] += g_a[((size_t)(b*400 + n0 + i))*256 + c];
    }
    __syncthreads();
    int warp = tid >> 5, lane = tid & 31;
    for (int i = warp; i < 32; i += 8) {
        if (n0 + i < 400) {
            float s1 = 0.f, s2 = 0.f;
            #pragma unroll
            for (int t = 0; t < 8; t++) { float v = sm[i][lane + t*32]; s1 += v; s2 += v*v; }
            #pragma unroll
            for (int off = 16; off > 0; off >>= 1) {
                s1 += __shfl_xor_sync(0xffffffffu, s1, off);
                s2 += __shfl_xor_sync(0xffffffffu, s2, off);
            }
            if (lane == 0) {
                float mu = s1 * (1.f/256.f);
                float var = s2 * (1.f/256.f) - mu*mu;
                smean[i] = mu; srs[i] = rsqrtf(var + 1e-6f);
            }
        }
    }
    __syncthreads();
    for (int j = tid; j < 8192; j += 256) {
        int i = j >> 8, c = j & 255;
        int n = n0 + i;
        if (n < 400)
            g_s[((size_t)(b*400 + n))*256 + c] = w[c]*(sm[i][c] - smean[i])*srs[i] + bias[c];
    }
}

// ---------------- SE gate (merged): mean over src spatial, then sigmoid(se_w . mean) ----------------
__global__ __launch_bounds__(512) void k_se(const float* __restrict__ src,
        const float* __restrict__ sew) {
    __shared__ float m[256];
    int b = blockIdx.x, tid = threadIdx.x;
    int warp = tid >> 5, lane = tid & 31;
    for (int c = warp; c < 256; c += 16) {
        float s = 0.f;
        for (int n = lane; n < 400; n += 32) s += src[(size_t)b*102400 + c*400 + n];
        #pragma unroll
        for (int off = 16; off > 0; off >>= 1) s += __shfl_xor_sync(0xffffffffu, s, off);
        if (lane == 0) m[c] = s * (1.f/400.f);
    }
    __syncthreads();
    float s = 0.f;
    const float* wr = sew + (size_t)tid*256;
    #pragma unroll 4
    for (int c = 0; c < 256; c++) s += wr[c]*m[c];
    g_se[b*512 + tid] = 1.f/(1.f + expf(-s));
}

// ---------------- 3x3 depthwise + exact GELU gate + SE ----------------
#define DW3_SMEM ((15488*2 + 288*2)*4)
__global__ __launch_bounds__(256) void k_dw3(const float* __restrict__ w) {
    int b = blockIdx.y, jt = blockIdx.x;  // jt in [0,16): tile of 32 channels
    extern __shared__ float sm[];
    float* t1 = sm;                 // [22*22][32] x1 half
    float* t2 = sm + 15488;         // [22*22][32] x2 half
    float* w1 = sm + 30976;         // [32][9]
    float* w2 = sm + 31264;         // [32][9]
    int tid = threadIdx.x;
    for (int i = tid; i < 288; i += 256) {
        int jj = i / 9, t = i % 9;
        w1[i] = w[(jt*32 + jj)*9 + t];
        w2[i] = w[(512 + jt*32 + jj)*9 + t];
    }
    for (int i = tid; i < 484*32; i += 256) {
        int pos = i >> 5, jj = i & 31;
        int y = pos / 22 - 1, x = pos % 22 - 1;
        float v1 = 0.f, v2 = 0.f;
        if (y >= 0 && y < 20 && x >= 0 && x < 20) {
            size_t base = ((size_t)(b*400 + y*20 + x))*1024 + jt*32 + jj;
            v1 = g_y[base]; v2 = g_y[base + 512];
        }
        t1[i] = v1; t2[i] = v2;
    }
    __syncthreads();
    for (int i = tid; i < 400*32; i += 256) {
        int pos = i >> 5, jj = i & 31;
        int y = pos / 20, x = pos % 20;
        float d1 = 0.f, d2 = 0.f;
        #pragma unroll
        for (int ky = 0; ky < 3; ky++)
            #pragma unroll
            for (int kx = 0; kx < 3; kx++) {
                int tp = ((y + ky)*22 + (x + kx))*32 + jj;
                d1 += w1[jj*9 + ky*3 + kx] * t1[tp];
                d2 += w2[jj*9 + ky*3 + kx] * t2[tp];
            }
        float ge = 0.5f * d1 * (1.f + erff(d1 * 0.70710678118654752f));
        g_h[((size_t)(b*400 + pos))*512 + jt*32 + jj] = ge * d2 * g_se[b*512 + jt*32 + jj];
    }
}

// ---------------- LN2: out = LN(s + f), output NCHW (B,C,N) ----------------
__global__ __launch_bounds__(256) void k_ln2(float* __restrict__ out,
        const float* __restrict__ w, const float* __restrict__ bias) {
    __shared__ float sm[32][257];
    __shared__ float smean[32], srs[32];
    int b = blockIdx.y, n0 = blockIdx.x * 32;
    int tid = threadIdx.x;
    for (int j = tid; j < 8192; j += 256) {
        int i = j >> 8, c = j & 255;
        int n = n0 + i;
        if (n < 400) {
            size_t bn = (size_t)(b*400 + n);
            sm[i][c] = g_s[bn*256 + c] + g_f[bn*256 + c];
        }
    }
    __syncthreads();
    int warp = tid >> 5, lane = tid & 31;
    for (int i = warp; i < 32; i += 8) {
        if (n0 + i < 400) {
            float s1 = 0.f, s2 = 0.f;
            #pragma unroll
            for (int t = 0; t < 8; t++) { float v = sm[i][lane + t*32]; s1 += v; s2 += v*v; }
            #pragma unroll
            for (int off = 16; off > 0; off >>= 1) {
                s1 += __shfl_xor_sync(0xffffffffu, s1, off);
                s2 += __shfl_xor_sync(0xffffffffu, s2, off);
            }
            if (lane == 0) {
                float mu = s1 * (1.f/256.f);
                float var = s2 * (1.f/256.f) - mu*mu;
                smean[i] = mu; srs[i] = rsqrtf(var + 1e-6f);
            }
        }
    }
    __syncthreads();
    for (int j = tid; j < 8192; j += 256) {
        int c = j >> 5, i = j & 31;
        int n = n0 + i;
        if (n < 400)
            out[(size_t)b*102400 + c*400 + n] = w[c]*(sm[i][c] - smean[i])*srs[i] + bias[c];
    }
}

// ---------------- host launch ----------------
extern "C" void kernel_launch(void* const* d_in, const int* in_sizes, int n_in,
                              void* d_out, int out_size) {
    const float* src    = (const float*)d_in[0];
    const float* qg_w   = (const float*)d_in[1];
    const float* qg_b   = (const float*)d_in[2];
    const float* kv_w   = (const float*)d_in[3];
    const float* kv_b   = (const float*)d_in[4];
    const float* proj_w = (const float*)d_in[5];
    const float* proj_b = (const float*)d_in[6];
    const float* dwc_w  = (const float*)d_in[7];
    const float* dwc_b  = (const float*)d_in[8];
    const float* power  = (const float*)d_in[9];
    const float* scale  = (const float*)d_in[10];
    const float* pos    = (const float*)d_in[11];
    const float* pin_w  = (const float*)d_in[12];
    const float* dw_w   = (const float*)d_in[13];
    const float* se_w   = (const float*)d_in[14];
    const float* pout_w = (const float*)d_in[15];
    const float* ln1_w  = (const float*)d_in[16];
    const float* ln1_b  = (const float*)d_in[17];
    const float* ln2_w  = (const float*)d_in[18];
    const float* ln2_b  = (const float*)d_in[19];
    float* out = (float*)d_out;

    float *px, *pqg, *pkv, *pfused, *pa, *ps, *py, *ph, *pf;
    cudaGetSymbolAddress((void**)&px, g_x);
    cudaGetSymbolAddress((void**)&pqg, g_qg);
    cudaGetSymbolAddress((void**)&pkv, g_kv);
    cudaGetSymbolAddress((void**)&pfused, g_fused);
    cudaGetSymbolAddress((void**)&pa, g_a);
    cudaGetSymbolAddress((void**)&ps, g_s);
    cudaGetSymbolAddress((void**)&py, g_y);
    cudaGetSymbolAddress((void**)&ph, g_h);
    cudaGetSymbolAddress((void**)&pf, g_f);

    cudaFuncSetAttribute(k_attn, cudaFuncAttributeMaxDynamicSharedMemorySize, ATTN_SMEM);
    cudaFuncSetAttribute(k_dwc5, cudaFuncAttributeMaxDynamicSharedMemorySize, DWC5_SMEM);
    cudaFuncSetAttribute(k_dw3,  cudaFuncAttributeMaxDynamicSharedMemorySize, DW3_SMEM);

    k_transpose<<<dim3(13, 64), 256>>>(src);

    tgemm128<<<dim3(4, 200), 256>>>(px, qg_w, qg_b, pqg, BN_TOT, 512, 256);
    tgemm128<<<dim3(4, 200), 256>>>(px, kv_w, kv_b, pkv, BN_TOT, 512, 256);

    k_attn<<<512, 512, ATTN_SMEM>>>(pos, scale, power);
    k_dwc5<<<512, 256, DWC5_SMEM>>>(dwc_w, dwc_b);

    tgemm128<<<dim3(2, 200), 256>>>(pfused, proj_w, proj_b, pa, BN_TOT, 256, 256);
    k_ln1<<<dim3(13, 64), 256>>>(src, ln1_w, ln1_b);

    k_se<<<64, 512>>>(src, se_w);

    tgemm128<<<dim3(8, 200), 256>>>(ps, pin_w, nullptr, py, BN_TOT, 1024, 256);
    k_dw3<<<dim3(16, 64), 256, DW3_SMEM>>>(dw_w);
    tgemm128<<<dim3(2, 200), 256>>>(ph, pout_w, nullptr, pf, BN_TOT, 256, 512);

    k_ln2<<<dim3(13, 64), 256>>>(out, ln2_w, ln2_b);
}